// round 11
// baseline (speedup 1.0000x reference)
#include <cuda_runtime.h>

// ---------------------------------------------------------------------------
// B=4, T=2048, C=1024, H=16, D=64.  All matmuls: mma.sync.m16n8k8.tf32.
// ldmatrix fragments, cp.async pipelines, pre-rounded tf32 inputs.
// GEMM: 128x128x32 tile, 4 warps (64x64 warp tile), 3 stages, 2 CTAs/SM.
// Attention: 128-q-row blocks, 8 warps, Qs aliased as Ps (warp-private rows),
//            2 CTAs/SM, two specialized diagonal tiles.
// ---------------------------------------------------------------------------

#define NBH 64
#define NT  2048
#define ND  64
#define NC  1024
#define NM  8192

__device__ float g_q[NBH * NT * ND];
__device__ float g_k[NBH * NT * ND];
__device__ float g_v[NBH * NT * ND];        // transposed: [bh][d][t]
__device__ float g_att[NM * NC];
__device__ float g_x[NM * NC];
__device__ float g_wqkv[3 * NC * NC];       // transposed: [n][k]
__device__ float g_wproj[NC * NC];          // transposed: [n][k]

__device__ __forceinline__ unsigned f2tf(float f) {
    unsigned u;
    asm("cvt.rna.tf32.f32 %0, %1;" : "=r"(u) : "f"(f));
    return u;
}
__device__ __forceinline__ float rtf(float x) { return __uint_as_float(f2tf(x)); }

__device__ __forceinline__ void mma_tf32(float* c, const unsigned* a,
                                         unsigned b0, unsigned b1) {
    asm volatile(
        "mma.sync.aligned.m16n8k8.row.col.f32.tf32.tf32.f32 "
        "{%0,%1,%2,%3}, {%4,%5,%6,%7}, {%8,%9}, {%0,%1,%2,%3};"
        : "+f"(c[0]), "+f"(c[1]), "+f"(c[2]), "+f"(c[3])
        : "r"(a[0]), "r"(a[1]), "r"(a[2]), "r"(a[3]), "r"(b0), "r"(b1));
}

__device__ __forceinline__ void ldsm4(unsigned* r, const float* p) {
    unsigned a = (unsigned)__cvta_generic_to_shared(p);
    asm volatile("ldmatrix.sync.aligned.m8n8.x4.shared.b16 {%0,%1,%2,%3}, [%4];"
                 : "=r"(r[0]), "=r"(r[1]), "=r"(r[2]), "=r"(r[3]) : "r"(a));
}

__device__ __forceinline__ void cp16(void* smem_dst, const void* gmem_src) {
    unsigned sa = (unsigned)__cvta_generic_to_shared(smem_dst);
    asm volatile("cp.async.cg.shared.global [%0], [%1], 16;" :: "r"(sa), "l"(gmem_src));
}
#define CPCOMMIT() asm volatile("cp.async.commit_group;")

__device__ __forceinline__ float fexp2(float x) {
    float y;
    asm("ex2.approx.f32 %0, %1;" : "=f"(y) : "f"(x));
    return y;
}

// swizzles (chunk = 4-float group within a row)
#define SWB(r, c) ((c) ^ ((r) & 7))          // rows of 32 floats (GEMM BK=32)
#define SWA(r, c) ((c) ^ ((r) & 7))          // rows of 64 floats (attention)

// ---------------------------------------------------------------------------
// pre-round kernels
// ---------------------------------------------------------------------------
__global__ void cvt_kernel(const float4* __restrict__ src,
                           uint4* __restrict__ dst, int n4)
{
    int i = blockIdx.x * 256 + threadIdx.x;
    if (i < n4) {
        float4 v = src[i];
        uint4 u;
        u.x = f2tf(v.x); u.y = f2tf(v.y); u.z = f2tf(v.z); u.w = f2tf(v.w);
        dst[i] = u;
    }
}

// round + transpose W[K][N] -> Wt[N][K]
__global__ void cvt_t_kernel(const float* __restrict__ src,
                             float* __restrict__ dst, int K, int N)
{
    __shared__ float t[32][33];
    const int n0 = blockIdx.x << 5;
    const int k0 = blockIdx.y << 5;
    const int tx = threadIdx.x & 31;
    const int ty = threadIdx.x >> 5;   // 0..7
#pragma unroll
    for (int j = 0; j < 4; j++)
        t[ty + j * 8][tx] = src[(size_t)(k0 + ty + j * 8) * N + n0 + tx];
    __syncthreads();
#pragma unroll
    for (int j = 0; j < 4; j++)
        dst[(size_t)(n0 + ty + j * 8) * K + k0 + tx] = rtf(t[tx][ty + j * 8]);
}

// ---------------------------------------------------------------------------
// GEMM: identical to Round 10 (128x128x32, 4 warps, 3-stage, 2 CTAs/SM).
// ---------------------------------------------------------------------------
#define BM 128
#define BN 128
#define BK 32
#define STG 3
#define ASZ (BM * BK)
#define BSZ (BN * BK)
#define GEMM_SMEM (STG * (ASZ + BSZ) * 4)   // 98304 B

template <int SCATTER>
__global__ void __launch_bounds__(128, 2) gemm_tc(
    const float* __restrict__ A, const float* __restrict__ Bt,
    float* __restrict__ C, int M, int N, int K)
{
    extern __shared__ float sh[];
    float* As = sh;
    float* Bs = sh + STG * ASZ;

    const int tid  = threadIdx.x;
    const int lane = tid & 31;
    const int w    = tid >> 5;        // 0..3
    const int wm   = w >> 1;          // 0..1 -> m*64
    const int wn   = w & 1;           // 0..1 -> n*64
    const int g    = lane >> 2;
    const int cq   = lane & 3;
    const int sub  = lane >> 3;       // 0..3 (ldmatrix sub-matrix)
    const int rl   = lane & 7;
    const int bm   = blockIdx.y << 7;
    const int bn   = blockIdx.x << 7;

    const int NIT = K >> 5;

    auto load_tile = [&](int kt, int s) {
        const float* Ag = A + (size_t)bm * K + kt * BK;
#pragma unroll
        for (int i = 0; i < 8; i++) {
            int idx = tid + i * 128;
            int r = idx >> 3, c = idx & 7;
            cp16(&As[s * ASZ + r * 32 + SWB(r, c) * 4], Ag + (size_t)r * K + c * 4);
        }
        const float* Bg = Bt + (size_t)bn * K + kt * BK;
#pragma unroll
        for (int i = 0; i < 8; i++) {
            int idx = tid + i * 128;
            int r = idx >> 3, c = idx & 7;
            cp16(&Bs[s * BSZ + r * 32 + SWB(r, c) * 4], Bg + (size_t)r * K + c * 4);
        }
    };

    float acc[4][8][4];
#pragma unroll
    for (int mi = 0; mi < 4; mi++)
#pragma unroll
        for (int ni = 0; ni < 8; ni++)
#pragma unroll
            for (int r = 0; r < 4; r++) acc[mi][ni][r] = 0.0f;

    load_tile(0, 0); CPCOMMIT();
    load_tile(1, 1); CPCOMMIT();

    int s_cur = 0, s_nxt = 2;
#pragma unroll 1
    for (int kt = 0; kt < NIT; kt++) {
        asm volatile("cp.async.wait_group 1;");
        __syncthreads();

        const float* Asb = As + s_cur * ASZ;
        const float* Bsb = Bs + s_cur * BSZ;
        const int s_pf = s_nxt;
        s_nxt = s_cur;
        s_cur = (s_cur == 2) ? 0 : s_cur + 1;

        auto do_chunk = [&](int ks) {
            const int chunk = ks * 2 + (sub >> 1);
            unsigned af[4][4], bf[4][4];
#pragma unroll
            for (int mi = 0; mi < 4; mi++) {
                const int row = wm * 64 + mi * 16 + (sub & 1) * 8 + rl;
                ldsm4(af[mi], Asb + row * 32 + SWB(row, chunk) * 4);
            }
#pragma unroll
            for (int p = 0; p < 4; p++) {
                const int row = wn * 64 + p * 16 + (sub & 1) * 8 + rl;
                ldsm4(bf[p], Bsb + row * 32 + SWB(row, chunk) * 4);
            }
#pragma unroll
            for (int mi = 0; mi < 4; mi++)
#pragma unroll
                for (int p = 0; p < 4; p++) {
                    mma_tf32(acc[mi][2 * p],     af[mi], bf[p][0], bf[p][2]);
                    mma_tf32(acc[mi][2 * p + 1], af[mi], bf[p][1], bf[p][3]);
                }
        };

        do_chunk(0);
        if (kt + 2 < NIT) load_tile(kt + 2, s_pf);
        CPCOMMIT();
#pragma unroll
        for (int ks = 1; ks < 4; ks++) do_chunk(ks);
    }

    // epilogue
#pragma unroll
    for (int mi = 0; mi < 4; mi++) {
        const int row = bm + wm * 64 + mi * 16 + g;
#pragma unroll
        for (int ni = 0; ni < 8; ni++) {
            const int col = bn + wn * 64 + ni * 8 + 2 * cq;
            if (SCATTER) {
                const int which = col >> 10;
                const int h     = (col & 1023) >> 6;
                const int d0    = col & 63;
                const int b     = row >> 11, t = row & 2047;
                if (which == 2) {
                    float* p = g_v + ((size_t)((b * 16 + h) * 64 + d0) << 11) + t;
                    p[0]            = rtf(acc[mi][ni][0]);
                    p[2048]         = rtf(acc[mi][ni][1]);
                    p[8]            = rtf(acc[mi][ni][2]);
                    p[2048 + 8]     = rtf(acc[mi][ni][3]);
                } else {
                    float* dst = (which == 0) ? g_q : g_k;
                    float* p = dst + ((size_t)((b * 16 + h) * 2048 + t) << 6) + d0;
                    *(float2*)p = make_float2(rtf(acc[mi][ni][0]), rtf(acc[mi][ni][1]));
                    *(float2*)(p + (8 << 6)) =
                        make_float2(rtf(acc[mi][ni][2]), rtf(acc[mi][ni][3]));
                }
            } else {
                *(float2*)&C[(size_t)row * N + col] =
                    make_float2(acc[mi][ni][0], acc[mi][ni][1]);
                *(float2*)&C[(size_t)(row + 8) * N + col] =
                    make_float2(acc[mi][ni][2], acc[mi][ni][3]);
            }
        }
    }
}

// ---------------------------------------------------------------------------
// Causal flash attention: 256 threads = 8 warps, 128 q rows/block, 2 CTAs/SM.
// QP region [128][64] holds Q for the prologue, then is reused as P storage
// (both accesses are warp-private rows -> __syncwarp suffices).
// K/V tiles double-buffered. V is [d][t]. Two specialized diagonal tiles.
// ---------------------------------------------------------------------------
#define AQP (128 * 64)
#define AKV (64 * 64)
#define ATTN_SMEM ((AQP + 4 * AKV) * 4)   // 98304 B
#define SCL 0.180336880f   // 0.125 * log2(e)

__global__ void __launch_bounds__(256, 2) attn_tc()
{
    extern __shared__ float sh[];
    float* QP = sh;                    // [128][64]  Q (prologue) then P
    float* Ks = sh + AQP;              // [2][64][64]  (rows = kpos)
    float* Vs = sh + AQP + 2 * AKV;    // [2][64][64]  (rows = d)

    const int tid  = threadIdx.x;
    const int lane = tid & 31;
    const int w    = tid >> 5;         // 0..7
    const int g    = lane >> 2;
    const int cq   = lane & 3;
    const int sub  = lane >> 3;
    const int rl   = lane & 7;
    const int bh   = blockIdx.y;
    const int q0   = (gridDim.x - 1 - blockIdx.x) << 7;   // big tiles first

    const float* Qg  = g_q + ((size_t)bh * NT + q0) * ND;
    const float* Kg0 = g_k + (size_t)bh * NT * ND;
    const float* Vg0 = g_v + (size_t)bh * ND * NT;   // [d][t]

    auto load_kv = [&](int kt, int s) {
        const float* Kg = Kg0 + ((size_t)kt << 12);
        const float* Vg = Vg0 + (kt << 6);
#pragma unroll
        for (int i = 0; i < 4; i++) {
            int idx = tid + i * 256;
            int r = idx >> 4, c = idx & 15;
            cp16(&Ks[s * AKV + r * 64 + SWA(r, c) * 4], Kg + r * 64 + c * 4);
            cp16(&Vs[s * AKV + r * 64 + SWA(r, c) * 4], Vg + (size_t)r * NT + c * 4);
        }
    };

    // Q (128 rows) + KV(0)
#pragma unroll
    for (int i = 0; i < 8; i++) {
        int idx = tid + i * 256;
        int r = idx >> 4, c = idx & 15;
        cp16(&QP[r * 64 + SWA(r, c) * 4], Qg + r * 64 + c * 4);
    }
    load_kv(0, 0);
    CPCOMMIT();
    asm volatile("cp.async.wait_group 0;");
    __syncthreads();

    const int rq    = w * 16 + g;                    // thread's q row (0..127)
    const int rowA  = w * 16 + (sub & 1) * 8 + rl;   // ldmatrix A row
    const int ktmax = (q0 >> 6) + 1;                 // last k-tile index

    // hoist Q fragments (loop-invariant; QP becomes P storage afterwards)
    unsigned qf[8][4];
#pragma unroll
    for (int ks = 0; ks < 8; ks++) {
        const int chunk = ks * 2 + (sub >> 1);
        ldsm4(qf[ks], QP + rowA * 64 + SWA(rowA, chunk) * 4);
    }
    __syncwarp();

    float m0 = -1e30f, m1 = -1e30f, l0 = 0.0f, l1 = 0.0f;
    float o[8][4];
#pragma unroll
    for (int nt = 0; nt < 8; nt++)
#pragma unroll
        for (int r = 0; r < 4; r++) o[nt][r] = 0.0f;

    // softmax + P store + PV for one tile; ntd = # active 8-col groups.
    auto softmax_pv = [&](const float* Vb, float s[8][4], int ntd) {
        float rm0 = -1e30f, rm1 = -1e30f;
#pragma unroll
        for (int nt = 0; nt < 8; nt++) {
            if (nt < ntd) {
                rm0 = fmaxf(rm0, fmaxf(s[nt][0], s[nt][1]));
                rm1 = fmaxf(rm1, fmaxf(s[nt][2], s[nt][3]));
            }
        }
        rm0 = fmaxf(rm0, __shfl_xor_sync(0xffffffffu, rm0, 1));
        rm0 = fmaxf(rm0, __shfl_xor_sync(0xffffffffu, rm0, 2));
        rm1 = fmaxf(rm1, __shfl_xor_sync(0xffffffffu, rm1, 1));
        rm1 = fmaxf(rm1, __shfl_xor_sync(0xffffffffu, rm1, 2));

        float mn0 = fmaxf(m0, rm0), mn1 = fmaxf(m1, rm1);
        float sc0 = fexp2(m0 - mn0), sc1 = fexp2(m1 - mn1);
        float rs0 = 0.0f, rs1 = 0.0f;
#pragma unroll
        for (int nt = 0; nt < 8; nt++) {
            if (nt < ntd) {
                s[nt][0] = fexp2(s[nt][0] - mn0);
                s[nt][1] = fexp2(s[nt][1] - mn0);
                s[nt][2] = fexp2(s[nt][2] - mn1);
                s[nt][3] = fexp2(s[nt][3] - mn1);
                rs0 += s[nt][0] + s[nt][1];
                rs1 += s[nt][2] + s[nt][3];
            }
        }
        rs0 += __shfl_xor_sync(0xffffffffu, rs0, 1);
        rs0 += __shfl_xor_sync(0xffffffffu, rs0, 2);
        rs1 += __shfl_xor_sync(0xffffffffu, rs1, 1);
        rs1 += __shfl_xor_sync(0xffffffffu, rs1, 2);
        l0 = l0 * sc0 + rs0;
        l1 = l1 * sc1 + rs1;
        m0 = mn0; m1 = mn1;
#pragma unroll
        for (int nt = 0; nt < 8; nt++) {
            o[nt][0] *= sc0; o[nt][1] *= sc0;
            o[nt][2] *= sc1; o[nt][3] *= sc1;
        }

        // P -> QP (warp-private rows), swizzled, rounded
#pragma unroll
        for (int nt = 0; nt < 8; nt++) {
            if (nt < ntd) {
                const int ch = nt * 2 + (cq >> 1);
                const int of = (2 * cq) & 3;
                *(float2*)&QP[rq * 64 + SWA(rq, ch) * 4 + of] =
                    make_float2(rtf(s[nt][0]), rtf(s[nt][1]));
                *(float2*)&QP[(rq + 8) * 64 + SWA(rq + 8, ch) * 4 + of] =
                    make_float2(rtf(s[nt][2]), rtf(s[nt][3]));
            }
        }
        __syncwarp();

        // O += P V  (V rows = d)
#pragma unroll
        for (int ks = 0; ks < 8; ks++) {
            if (ks < ntd) {
                const int chunk = ks * 2 + (sub >> 1);
                unsigned ap[4];
                ldsm4(ap, QP + rowA * 64 + SWA(rowA, chunk) * 4);
#pragma unroll
                for (int p = 0; p < 4; p++) {
                    const int rv = p * 16 + (sub & 1) * 8 + rl;
                    unsigned bv[4];
                    ldsm4(bv, Vb + rv * 64 + SWA(rv, chunk) * 4);
                    mma_tf32(o[2 * p],     ap, bv[0], bv[2]);
                    mma_tf32(o[2 * p + 1], ap, bv[1], bv[3]);
                }
            }
        }
        __syncwarp();
    };

    // ---------------- main loop: fully unmasked tiles 0..ktmax-2 ----------
    for (int kt = 0; kt < ktmax - 1; kt++) {
        const float* Kb = Ks + (kt & 1) * AKV;
        const float* Vb = Vs + (kt & 1) * AKV;

        float s[8][4];
#pragma unroll
        for (int nt = 0; nt < 8; nt++)
#pragma unroll
            for (int r = 0; r < 4; r++) s[nt][r] = 0.0f;

        {
            const int chunk = (sub >> 1);
#pragma unroll
            for (int p = 0; p < 4; p++) {
                const int rk = p * 16 + (sub & 1) * 8 + rl;
                unsigned bk[4];
                ldsm4(bk, Kb + rk * 64 + SWA(rk, chunk) * 4);
                mma_tf32(s[2 * p],     qf[0], bk[0], bk[2]);
                mma_tf32(s[2 * p + 1], qf[0], bk[1], bk[3]);
            }
        }
        load_kv(kt + 1, (kt + 1) & 1);
        CPCOMMIT();
#pragma unroll
        for (int ks = 1; ks < 8; ks++) {
            const int chunk = ks * 2 + (sub >> 1);
#pragma unroll
            for (int p = 0; p < 4; p++) {
                const int rk = p * 16 + (sub & 1) * 8 + rl;
                unsigned bk[4];
                ldsm4(bk, Kb + rk * 64 + SWA(rk, chunk) * 4);
                mma_tf32(s[2 * p],     qf[ks], bk[0], bk[2]);
                mma_tf32(s[2 * p + 1], qf[ks], bk[1], bk[3]);
            }
        }

#pragma unroll
        for (int nt = 0; nt < 8; nt++)
#pragma unroll
            for (int r = 0; r < 4; r++) s[nt][r] *= SCL;

        softmax_pv(Vb, s, 8);

        asm volatile("cp.async.wait_group 0;");
        __syncthreads();
    }

    // ---------------- diagonal tile A (kt = ktmax-1): cols q0..q0+63 ------
    {
        const int kt = ktmax - 1;
        const float* Kb = Ks + (kt & 1) * AKV;
        const float* Vb = Vs + (kt & 1) * AKV;
        const int ntd = (w < 4) ? (2 * w + 2) : 8;

        float s[8][4];
#pragma unroll
        for (int nt = 0; nt < 8; nt++)
#pragma unroll
            for (int r = 0; r < 4; r++) s[nt][r] = 0.0f;

        {
            const int chunk = (sub >> 1);
#pragma unroll
            for (int p = 0; p < 4; p++) {
                if (p <= w) {
                    const int rk = p * 16 + (sub & 1) * 8 + rl;
                    unsigned bk[4];
                    ldsm4(bk, Kb + rk * 64 + SWA(rk, chunk) * 4);
                    mma_tf32(s[2 * p],     qf[0], bk[0], bk[2]);
                    mma_tf32(s[2 * p + 1], qf[0], bk[1], bk[3]);
                }
            }
        }
        load_kv(ktmax, ktmax & 1);
        CPCOMMIT();
#pragma unroll
        for (int ks = 1; ks < 8; ks++) {
            const int chunk = ks * 2 + (sub >> 1);
#pragma unroll
            for (int p = 0; p < 4; p++) {
                if (p <= w) {
                    const int rk = p * 16 + (sub & 1) * 8 + rl;
                    unsigned bk[4];
                    ldsm4(bk, Kb + rk * 64 + SWA(rk, chunk) * 4);
                    mma_tf32(s[2 * p],     qf[ks], bk[0], bk[2]);
                    mma_tf32(s[2 * p + 1], qf[ks], bk[1], bk[3]);
                }
            }
        }

        // scale + causal mask (col <= rq; trivially true for w>=4)
#pragma unroll
        for (int nt = 0; nt < 8; nt++) {
            if (nt < ntd) {
                int gc = nt * 8 + 2 * cq;
                s[nt][0] = (gc     <= rq)     ? s[nt][0] * SCL : -1e30f;
                s[nt][1] = (gc + 1 <= rq)     ? s[nt][1] * SCL : -1e30f;
                s[nt][2] = (gc     <= rq + 8) ? s[nt][2] * SCL : -1e30f;
                s[nt][3] = (gc + 1 <= rq + 8) ? s[nt][3] * SCL : -1e30f;
            }
        }

        softmax_pv(Vb, s, ntd);

        asm volatile("cp.async.wait_group 0;");
        __syncthreads();
    }

    // ---------------- diagonal tile B (kt = ktmax): cols q0+64..q0+127 ----
    if (w >= 4) {
        const float* Kb = Ks + (ktmax & 1) * AKV;
        const float* Vb = Vs + (ktmax & 1) * AKV;
        const int wz   = w - 4;
        const int ntd  = 2 * wz + 2;
        const int rloc = rq - 64;   // row within this tile's col space

        float s[8][4];
#pragma unroll
        for (int nt = 0; nt < 8; nt++)
#pragma unroll
            for (int r = 0; r < 4; r++) s[nt][r] = 0.0f;

#pragma unroll
        for (int ks = 0; ks < 8; ks++) {
            const int chunk = ks * 2 + (sub >> 1);
#pragma unroll
            for (int p = 0; p < 4; p++) {
                if (p <= wz) {
                    const int rk = p * 16 + (sub & 1) * 8 + rl;
                    unsigned bk[4];
                    ldsm4(bk, Kb + rk * 64 + SWA(rk, chunk) * 4);
                    mma_tf32(s[2 * p],     qf[ks], bk[0], bk[2]);
                    mma_tf32(s[2 * p + 1], qf[ks], bk[1], bk[3]);
                }
            }
        }

#pragma unroll
        for (int nt = 0; nt < 8; nt++) {
            if (nt < ntd) {
                int gc = nt * 8 + 2 * cq;
                s[nt][0] = (gc     <= rloc)     ? s[nt][0] * SCL : -1e30f;
                s[nt][1] = (gc + 1 <= rloc)     ? s[nt][1] * SCL : -1e30f;
                s[nt][2] = (gc     <= rloc + 8) ? s[nt][2] * SCL : -1e30f;
                s[nt][3] = (gc + 1 <= rloc + 8) ? s[nt][3] * SCL : -1e30f;
            }
        }

        softmax_pv(Vb, s, ntd);
    }

    // epilogue
    const int b = bh >> 4;
    const int h = bh & 15;
    const float inv0 = 1.0f / l0;
    const float inv1 = 1.0f / l1;
    float* Og = g_att + ((size_t)(b * NT + q0 + rq)) * NC + (h << 6);
#pragma unroll
    for (int nt = 0; nt < 8; nt++) {
        int col = nt * 8 + 2 * cq;
        *(float2*)(Og + col) =
            make_float2(rtf(o[nt][0] * inv0), rtf(o[nt][1] * inv0));
        *(float2*)(Og + (size_t)8 * NC + col) =
            make_float2(rtf(o[nt][2] * inv1), rtf(o[nt][3] * inv1));
    }
}

// ---------------------------------------------------------------------------
// launch
// ---------------------------------------------------------------------------
extern "C" void kernel_launch(void* const* d_in, const int* in_sizes, int n_in,
                              void* d_out, int out_size)
{
    const float* x     = (const float*)d_in[0];
    const float* Wqkv  = (const float*)d_in[1];
    const float* Wproj = (const float*)d_in[2];
    float* out = (float*)d_out;

    void *px, *pwqkv, *pwproj, *patt;
    cudaGetSymbolAddress(&px, g_x);
    cudaGetSymbolAddress(&pwqkv, g_wqkv);
    cudaGetSymbolAddress(&pwproj, g_wproj);
    cudaGetSymbolAddress(&patt, g_att);

    cudaFuncSetAttribute(gemm_tc<1>,
                         cudaFuncAttributeMaxDynamicSharedMemorySize, GEMM_SMEM);
    cudaFuncSetAttribute(gemm_tc<0>,
                         cudaFuncAttributeMaxDynamicSharedMemorySize, GEMM_SMEM);
    cudaFuncSetAttribute(attn_tc,
                         cudaFuncAttributeMaxDynamicSharedMemorySize, ATTN_SMEM);

    // 0) pre-round x; round+transpose weights to [n][k]
    cvt_kernel<<<(NM * NC / 4 + 255) / 256, 256>>>(
        (const float4*)x, (uint4*)px, NM * NC / 4);
    cvt_t_kernel<<<dim3(3 * NC / 32, NC / 32), 256>>>(
        Wqkv, (float*)pwqkv, NC, 3 * NC);
    cvt_t_kernel<<<dim3(NC / 32, NC / 32), 256>>>(
        Wproj, (float*)pwproj, NC, NC);

    // 1) qkv = x @ Wqkv -> scatter q,k [bh][t][d], v [bh][d][t]
    gemm_tc<1><<<dim3(3 * NC / BN, NM / BM), 128, GEMM_SMEM>>>(
        (const float*)px, (const float*)pwqkv, nullptr, NM, 3 * NC, NC);

    // 2) causal attention -> g_att (rounded)
    attn_tc<<<dim3(NT / 128, NBH), 256, ATTN_SMEM>>>();

    // 3) out = g_att @ Wproj
    gemm_tc<0><<<dim3(NC / BN, NM / BM), 128, GEMM_SMEM>>>(
        (const float*)patt, (const float*)pwproj, out, NM, NC, NC);
}

// round 12
// speedup vs baseline: 1.0387x; 1.0387x over previous
#include <cuda_runtime.h>

// ---------------------------------------------------------------------------
// B=4, T=2048, C=1024, H=16, D=64.  All matmuls: mma.sync.m16n8k8.tf32.
// ldmatrix fragments, cp.async pipelines, pre-rounded tf32 inputs.
// GEMM: 128x128x32 tile, 4 warps (64x64 warp tile), 3 stages, 2 CTAs/SM,
//       register fragment double-buffering across k-chunks.
// Attention: exact Round-10 structure (64-q blocks, 2 CTAs/SM).
// ---------------------------------------------------------------------------

#define NBH 64
#define NT  2048
#define ND  64
#define NC  1024
#define NM  8192

__device__ float g_q[NBH * NT * ND];
__device__ float g_k[NBH * NT * ND];
__device__ float g_v[NBH * NT * ND];        // transposed: [bh][d][t]
__device__ float g_att[NM * NC];
__device__ float g_x[NM * NC];
__device__ float g_wqkv[3 * NC * NC];       // transposed: [n][k]
__device__ float g_wproj[NC * NC];          // transposed: [n][k]

__device__ __forceinline__ unsigned f2tf(float f) {
    unsigned u;
    asm("cvt.rna.tf32.f32 %0, %1;" : "=r"(u) : "f"(f));
    return u;
}
__device__ __forceinline__ float rtf(float x) { return __uint_as_float(f2tf(x)); }

__device__ __forceinline__ void mma_tf32(float* c, const unsigned* a,
                                         unsigned b0, unsigned b1) {
    asm volatile(
        "mma.sync.aligned.m16n8k8.row.col.f32.tf32.tf32.f32 "
        "{%0,%1,%2,%3}, {%4,%5,%6,%7}, {%8,%9}, {%0,%1,%2,%3};"
        : "+f"(c[0]), "+f"(c[1]), "+f"(c[2]), "+f"(c[3])
        : "r"(a[0]), "r"(a[1]), "r"(a[2]), "r"(a[3]), "r"(b0), "r"(b1));
}

__device__ __forceinline__ void ldsm4(unsigned* r, const float* p) {
    unsigned a = (unsigned)__cvta_generic_to_shared(p);
    asm volatile("ldmatrix.sync.aligned.m8n8.x4.shared.b16 {%0,%1,%2,%3}, [%4];"
                 : "=r"(r[0]), "=r"(r[1]), "=r"(r[2]), "=r"(r[3]) : "r"(a));
}

__device__ __forceinline__ void cp16(void* smem_dst, const void* gmem_src) {
    unsigned sa = (unsigned)__cvta_generic_to_shared(smem_dst);
    asm volatile("cp.async.cg.shared.global [%0], [%1], 16;" :: "r"(sa), "l"(gmem_src));
}
#define CPCOMMIT() asm volatile("cp.async.commit_group;")

__device__ __forceinline__ float fexp2(float x) {
    float y;
    asm("ex2.approx.f32 %0, %1;" : "=f"(y) : "f"(x));
    return y;
}

// swizzles (chunk = 4-float group within a row)
#define SWB(r, c) ((c) ^ ((r) & 7))          // rows of 32 floats (GEMM BK=32)
#define SWA(r, c) ((c) ^ ((r) & 7))          // rows of 64 floats (attention)

// ---------------------------------------------------------------------------
// pre-round kernels
// ---------------------------------------------------------------------------
__global__ void cvt_kernel(const float4* __restrict__ src,
                           uint4* __restrict__ dst, int n4)
{
    int i = blockIdx.x * 256 + threadIdx.x;
    if (i < n4) {
        float4 v = src[i];
        uint4 u;
        u.x = f2tf(v.x); u.y = f2tf(v.y); u.z = f2tf(v.z); u.w = f2tf(v.w);
        dst[i] = u;
    }
}

// round + transpose W[K][N] -> Wt[N][K]
__global__ void cvt_t_kernel(const float* __restrict__ src,
                             float* __restrict__ dst, int K, int N)
{
    __shared__ float t[32][33];
    const int n0 = blockIdx.x << 5;
    const int k0 = blockIdx.y << 5;
    const int tx = threadIdx.x & 31;
    const int ty = threadIdx.x >> 5;   // 0..7
#pragma unroll
    for (int j = 0; j < 4; j++)
        t[ty + j * 8][tx] = src[(size_t)(k0 + ty + j * 8) * N + n0 + tx];
    __syncthreads();
#pragma unroll
    for (int j = 0; j < 4; j++)
        dst[(size_t)(n0 + ty + j * 8) * K + k0 + tx] = rtf(t[tx][ty + j * 8]);
}

// ---------------------------------------------------------------------------
// GEMM: 128m x 128n x 32k tile, 128 threads (4 warps 2x2, warp tile 64x64),
// 3-stage cp.async, 2 CTAs/SM, fragment double-buffering.
// SCATTER=1: round + scatter q/k into [bh][t][d], v into [bh][d][t].
// ---------------------------------------------------------------------------
#define BM 128
#define BN 128
#define BK 32
#define STG 3
#define ASZ (BM * BK)
#define BSZ (BN * BK)
#define GEMM_SMEM (STG * (ASZ + BSZ) * 4)   // 98304 B

template <int SCATTER>
__global__ void __launch_bounds__(128, 2) gemm_tc(
    const float* __restrict__ A, const float* __restrict__ Bt,
    float* __restrict__ C, int M, int N, int K)
{
    extern __shared__ float sh[];
    float* As = sh;
    float* Bs = sh + STG * ASZ;

    const int tid  = threadIdx.x;
    const int lane = tid & 31;
    const int w    = tid >> 5;        // 0..3
    const int wm   = w >> 1;          // 0..1 -> m*64
    const int wn   = w & 1;           // 0..1 -> n*64
    const int g    = lane >> 2;
    const int cq   = lane & 3;
    const int sub  = lane >> 3;       // 0..3 (ldmatrix sub-matrix)
    const int rl   = lane & 7;
    const int bm   = blockIdx.y << 7;
    const int bn   = blockIdx.x << 7;

    const int NIT = K >> 5;
    const int rowAm = wm * 64 + (sub & 1) * 8 + rl;   // base A ldsm row (+16*mi)
    const int rowBn = wn * 64 + (sub & 1) * 8 + rl;   // base B ldsm row (+16*p)

    auto load_tile = [&](int kt, int s) {
        const float* Ag = A + (size_t)bm * K + kt * BK;
#pragma unroll
        for (int i = 0; i < 8; i++) {
            int idx = tid + i * 128;
            int r = idx >> 3, c = idx & 7;
            cp16(&As[s * ASZ + r * 32 + SWB(r, c) * 4], Ag + (size_t)r * K + c * 4);
        }
        const float* Bg = Bt + (size_t)bn * K + kt * BK;
#pragma unroll
        for (int i = 0; i < 8; i++) {
            int idx = tid + i * 128;
            int r = idx >> 3, c = idx & 7;
            cp16(&Bs[s * BSZ + r * 32 + SWB(r, c) * 4], Bg + (size_t)r * K + c * 4);
        }
    };

    float acc[4][8][4];
#pragma unroll
    for (int mi = 0; mi < 4; mi++)
#pragma unroll
        for (int ni = 0; ni < 8; ni++)
#pragma unroll
            for (int r = 0; r < 4; r++) acc[mi][ni][r] = 0.0f;

    load_tile(0, 0); CPCOMMIT();
    load_tile(1, 1); CPCOMMIT();

    unsigned af[2][4][4], bf[2][4][4];

    int s_cur = 0, s_nxt = 2;
#pragma unroll 1
    for (int kt = 0; kt < NIT; kt++) {
        asm volatile("cp.async.wait_group 1;");
        __syncthreads();

        const float* Asb = As + s_cur * ASZ;
        const float* Bsb = Bs + s_cur * BSZ;
        const int s_pf = s_nxt;
        s_nxt = s_cur;
        s_cur = (s_cur == 2) ? 0 : s_cur + 1;

        auto load_frags = [&](int ks, int buf) {
            const int chunk = ks * 2 + (sub >> 1);
#pragma unroll
            for (int mi = 0; mi < 4; mi++) {
                const int row = rowAm + mi * 16;
                ldsm4(af[buf][mi], Asb + row * 32 + SWB(row, chunk) * 4);
            }
#pragma unroll
            for (int p = 0; p < 4; p++) {
                const int row = rowBn + p * 16;
                ldsm4(bf[buf][p], Bsb + row * 32 + SWB(row, chunk) * 4);
            }
        };
        auto do_mma = [&](int buf) {
#pragma unroll
            for (int mi = 0; mi < 4; mi++)
#pragma unroll
                for (int p = 0; p < 4; p++) {
                    mma_tf32(acc[mi][2 * p],     af[buf][mi], bf[buf][p][0], bf[buf][p][2]);
                    mma_tf32(acc[mi][2 * p + 1], af[buf][mi], bf[buf][p][1], bf[buf][p][3]);
                }
        };

        // frag pipeline: ldsm chunk0; issue gmem prefetch; then for each
        // chunk: ldsm next chunk's frags BEFORE this chunk's MMAs.
        load_frags(0, 0);
        if (kt + 2 < NIT) load_tile(kt + 2, s_pf);
        CPCOMMIT();
#pragma unroll
        for (int ks = 0; ks < 4; ks++) {
            if (ks < 3) load_frags(ks + 1, (ks + 1) & 1);
            do_mma(ks & 1);
        }
    }

    // epilogue
#pragma unroll
    for (int mi = 0; mi < 4; mi++) {
        const int row = bm + wm * 64 + mi * 16 + g;
#pragma unroll
        for (int ni = 0; ni < 8; ni++) {
            const int col = bn + wn * 64 + ni * 8 + 2 * cq;
            if (SCATTER) {
                const int which = col >> 10;
                const int h     = (col & 1023) >> 6;
                const int d0    = col & 63;
                const int b     = row >> 11, t = row & 2047;
                if (which == 2) {
                    float* p = g_v + ((size_t)((b * 16 + h) * 64 + d0) << 11) + t;
                    p[0]            = rtf(acc[mi][ni][0]);
                    p[2048]         = rtf(acc[mi][ni][1]);
                    p[8]            = rtf(acc[mi][ni][2]);
                    p[2048 + 8]     = rtf(acc[mi][ni][3]);
                } else {
                    float* dst = (which == 0) ? g_q : g_k;
                    float* p = dst + ((size_t)((b * 16 + h) * 2048 + t) << 6) + d0;
                    *(float2*)p = make_float2(rtf(acc[mi][ni][0]), rtf(acc[mi][ni][1]));
                    *(float2*)(p + (8 << 6)) =
                        make_float2(rtf(acc[mi][ni][2]), rtf(acc[mi][ni][3]));
                }
            } else {
                *(float2*)&C[(size_t)row * N + col] =
                    make_float2(acc[mi][ni][0], acc[mi][ni][1]);
                *(float2*)&C[(size_t)(row + 8) * N + col] =
                    make_float2(acc[mi][ni][2], acc[mi][ni][3]);
            }
        }
    }
}

// ---------------------------------------------------------------------------
// Causal flash attention (exact Round-10 structure): 128 threads = 4 warps,
// 64 q rows/block, 2 CTAs/SM. Q frags hoisted, diagonal specialized,
// reversed launch order.
// ---------------------------------------------------------------------------
#define AQ  (64 * 64)
#define AKV (64 * 64)
#define ATTN_SMEM ((AQ + 4 * AKV + 64 * 64) * 4)   // 98304 B
#define SCL 0.180336880f   // 0.125 * log2(e)

__global__ void __launch_bounds__(128, 2) attn_tc()
{
    extern __shared__ float sh[];
    float* Qs = sh;                    // [64][64]
    float* Ks = sh + AQ;               // [2][64][64]  (rows = kpos)
    float* Vs = sh + AQ + 2 * AKV;     // [2][64][64]  (rows = d)
    float* Ps = sh + AQ + 4 * AKV;     // [64][64]

    const int tid  = threadIdx.x;
    const int lane = tid & 31;
    const int w    = tid >> 5;         // 0..3
    const int g    = lane >> 2;
    const int cq   = lane & 3;
    const int sub  = lane >> 3;
    const int rl   = lane & 7;
    const int bh   = blockIdx.y;
    const int q0   = (gridDim.x - 1 - blockIdx.x) << 6;   // big tiles first

    const float* Qg  = g_q + ((size_t)bh * NT + q0) * ND;
    const float* Kg0 = g_k + (size_t)bh * NT * ND;
    const float* Vg0 = g_v + (size_t)bh * ND * NT;   // [d][t]

    auto load_kv = [&](int kt, int s) {
        const float* Kg = Kg0 + ((size_t)kt << 12);
        const float* Vg = Vg0 + (kt << 6);
#pragma unroll
        for (int i = 0; i < 8; i++) {
            int idx = tid + i * 128;
            int r = idx >> 4, c = idx & 15;
            cp16(&Ks[s * AKV + r * 64 + SWA(r, c) * 4], Kg + r * 64 + c * 4);
            cp16(&Vs[s * AKV + r * 64 + SWA(r, c) * 4], Vg + (size_t)r * NT + c * 4);
        }
    };

    // Q + KV(0) in group 0
#pragma unroll
    for (int i = 0; i < 8; i++) {
        int idx = tid + i * 128;
        int r = idx >> 4, c = idx & 15;
        cp16(&Qs[r * 64 + SWA(r, c) * 4], Qg + r * 64 + c * 4);
    }
    load_kv(0, 0);
    CPCOMMIT();
    asm volatile("cp.async.wait_group 0;");
    __syncthreads();

    const int rq    = w * 16 + g;
    const int rowA  = w * 16 + (sub & 1) * 8 + rl;   // ldmatrix A row
    const int ktmax = q0 >> 6;
    const int NTD   = 2 * w + 2;   // diag: kpos 8-tiles needed by this warp

    // hoist Q fragments (loop-invariant)
    unsigned qf[8][4];
#pragma unroll
    for (int ks = 0; ks < 8; ks++) {
        const int chunk = ks * 2 + (sub >> 1);
        ldsm4(qf[ks], Qs + rowA * 64 + SWA(rowA, chunk) * 4);
    }

    float m0 = -1e30f, m1 = -1e30f, l0 = 0.0f, l1 = 0.0f;
    float o[8][4];
#pragma unroll
    for (int nt = 0; nt < 8; nt++)
#pragma unroll
        for (int r = 0; r < 4; r++) o[nt][r] = 0.0f;

    // ---------------- main loop: non-diagonal tiles (no masking) ----------
    for (int kt = 0; kt < ktmax; kt++) {
        const float* Kb = Ks + (kt & 1) * AKV;
        const float* Vb = Vs + (kt & 1) * AKV;

        float s[8][4];
#pragma unroll
        for (int nt = 0; nt < 8; nt++)
#pragma unroll
            for (int r = 0; r < 4; r++) s[nt][r] = 0.0f;

        // S chunk ks=0, then issue next K/V prefetch, then chunks 1..7
        {
            const int chunk = (sub >> 1);
#pragma unroll
            for (int p = 0; p < 4; p++) {
                const int rk = p * 16 + (sub & 1) * 8 + rl;
                unsigned bk[4];
                ldsm4(bk, Kb + rk * 64 + SWA(rk, chunk) * 4);
                mma_tf32(s[2 * p],     qf[0], bk[0], bk[2]);
                mma_tf32(s[2 * p + 1], qf[0], bk[1], bk[3]);
            }
        }
        load_kv(kt + 1, (kt + 1) & 1);
        CPCOMMIT();
#pragma unroll
        for (int ks = 1; ks < 8; ks++) {
            const int chunk = ks * 2 + (sub >> 1);
#pragma unroll
            for (int p = 0; p < 4; p++) {
                const int rk = p * 16 + (sub & 1) * 8 + rl;
                unsigned bk[4];
                ldsm4(bk, Kb + rk * 64 + SWA(rk, chunk) * 4);
                mma_tf32(s[2 * p],     qf[ks], bk[0], bk[2]);
                mma_tf32(s[2 * p + 1], qf[ks], bk[1], bk[3]);
            }
        }

#pragma unroll
        for (int nt = 0; nt < 8; nt++)
#pragma unroll
            for (int r = 0; r < 4; r++) s[nt][r] *= SCL;

        // online softmax (log2 domain)
        float rm0 = -1e30f, rm1 = -1e30f;
#pragma unroll
        for (int nt = 0; nt < 8; nt++) {
            rm0 = fmaxf(rm0, fmaxf(s[nt][0], s[nt][1]));
            rm1 = fmaxf(rm1, fmaxf(s[nt][2], s[nt][3]));
        }
        rm0 = fmaxf(rm0, __shfl_xor_sync(0xffffffffu, rm0, 1));
        rm0 = fmaxf(rm0, __shfl_xor_sync(0xffffffffu, rm0, 2));
        rm1 = fmaxf(rm1, __shfl_xor_sync(0xffffffffu, rm1, 1));
        rm1 = fmaxf(rm1, __shfl_xor_sync(0xffffffffu, rm1, 2));

        float mn0 = fmaxf(m0, rm0), mn1 = fmaxf(m1, rm1);
        float sc0 = fexp2(m0 - mn0), sc1 = fexp2(m1 - mn1);
        float rs0 = 0.0f, rs1 = 0.0f;
#pragma unroll
        for (int nt = 0; nt < 8; nt++) {
            s[nt][0] = fexp2(s[nt][0] - mn0);
            s[nt][1] = fexp2(s[nt][1] - mn0);
            s[nt][2] = fexp2(s[nt][2] - mn1);
            s[nt][3] = fexp2(s[nt][3] - mn1);
            rs0 += s[nt][0] + s[nt][1];
            rs1 += s[nt][2] + s[nt][3];
        }
        rs0 += __shfl_xor_sync(0xffffffffu, rs0, 1);
        rs0 += __shfl_xor_sync(0xffffffffu, rs0, 2);
        rs1 += __shfl_xor_sync(0xffffffffu, rs1, 1);
        rs1 += __shfl_xor_sync(0xffffffffu, rs1, 2);
        l0 = l0 * sc0 + rs0;
        l1 = l1 * sc1 + rs1;
        m0 = mn0; m1 = mn1;
#pragma unroll
        for (int nt = 0; nt < 8; nt++) {
            o[nt][0] *= sc0; o[nt][1] *= sc0;
            o[nt][2] *= sc1; o[nt][3] *= sc1;
        }

        // P -> smem (warp-private rows), swizzled, rounded
#pragma unroll
        for (int nt = 0; nt < 8; nt++) {
            const int ch = nt * 2 + (cq >> 1);
            const int of = (2 * cq) & 3;
            *(float2*)&Ps[rq * 64 + SWA(rq, ch) * 4 + of] =
                make_float2(rtf(s[nt][0]), rtf(s[nt][1]));
            *(float2*)&Ps[(rq + 8) * 64 + SWA(rq + 8, ch) * 4 + of] =
                make_float2(rtf(s[nt][2]), rtf(s[nt][3]));
        }
        __syncwarp();

        // O += P V   (V is [d][t] in smem: rows = d)
#pragma unroll
        for (int ks = 0; ks < 8; ks++) {
            const int chunk = ks * 2 + (sub >> 1);
            unsigned ap[4];
            ldsm4(ap, Ps + rowA * 64 + SWA(rowA, chunk) * 4);
#pragma unroll
            for (int p = 0; p < 4; p++) {
                const int rv = p * 16 + (sub & 1) * 8 + rl;   // d row
                unsigned bv[4];
                ldsm4(bv, Vb + rv * 64 + SWA(rv, chunk) * 4);
                mma_tf32(o[2 * p],     ap, bv[0], bv[2]);
                mma_tf32(o[2 * p + 1], ap, bv[1], bv[3]);
            }
        }

        asm volatile("cp.async.wait_group 0;");
        __syncthreads();
    }

    // ---------------- diagonal tile (kt == ktmax), per-warp reduced range --
    {
        const float* Kb = Ks + (ktmax & 1) * AKV;
        const float* Vb = Vs + (ktmax & 1) * AKV;

        float s[8][4];
#pragma unroll
        for (int nt = 0; nt < 8; nt++)
#pragma unroll
            for (int r = 0; r < 4; r++) s[nt][r] = 0.0f;

        // S: only kpos tile-pairs p <= w needed (warp-uniform guard)
#pragma unroll
        for (int ks = 0; ks < 8; ks++) {
            const int chunk = ks * 2 + (sub >> 1);
#pragma unroll
            for (int p = 0; p < 4; p++) {
                if (p <= w) {
                    const int rk = p * 16 + (sub & 1) * 8 + rl;
                    unsigned bk[4];
                    ldsm4(bk, Kb + rk * 64 + SWA(rk, chunk) * 4);
                    mma_tf32(s[2 * p],     qf[ks], bk[0], bk[2]);
                    mma_tf32(s[2 * p + 1], qf[ks], bk[1], bk[3]);
                }
            }
        }

        // scale + causal mask (nt < NTD only)
        const int r0 = rq, r1 = rq + 8;
#pragma unroll
        for (int nt = 0; nt < 8; nt++) {
            if (nt < NTD) {
                int gc = nt * 8 + 2 * cq;
                s[nt][0] = (gc     <= r0) ? s[nt][0] * SCL : -1e30f;
                s[nt][1] = (gc + 1 <= r0) ? s[nt][1] * SCL : -1e30f;
                s[nt][2] = (gc     <= r1) ? s[nt][2] * SCL : -1e30f;
                s[nt][3] = (gc + 1 <= r1) ? s[nt][3] * SCL : -1e30f;
            }
        }

        float rm0 = -1e30f, rm1 = -1e30f;
#pragma unroll
        for (int nt = 0; nt < 8; nt++) {
            if (nt < NTD) {
                rm0 = fmaxf(rm0, fmaxf(s[nt][0], s[nt][1]));
                rm1 = fmaxf(rm1, fmaxf(s[nt][2], s[nt][3]));
            }
        }
        rm0 = fmaxf(rm0, __shfl_xor_sync(0xffffffffu, rm0, 1));
        rm0 = fmaxf(rm0, __shfl_xor_sync(0xffffffffu, rm0, 2));
        rm1 = fmaxf(rm1, __shfl_xor_sync(0xffffffffu, rm1, 1));
        rm1 = fmaxf(rm1, __shfl_xor_sync(0xffffffffu, rm1, 2));

        float mn0 = fmaxf(m0, rm0), mn1 = fmaxf(m1, rm1);
        float sc0 = fexp2(m0 - mn0), sc1 = fexp2(m1 - mn1);
        float rs0 = 0.0f, rs1 = 0.0f;
#pragma unroll
        for (int nt = 0; nt < 8; nt++) {
            if (nt < NTD) {
                s[nt][0] = fexp2(s[nt][0] - mn0);
                s[nt][1] = fexp2(s[nt][1] - mn0);
                s[nt][2] = fexp2(s[nt][2] - mn1);
                s[nt][3] = fexp2(s[nt][3] - mn1);
                rs0 += s[nt][0] + s[nt][1];
                rs1 += s[nt][2] + s[nt][3];
            }
        }
        rs0 += __shfl_xor_sync(0xffffffffu, rs0, 1);
        rs0 += __shfl_xor_sync(0xffffffffu, rs0, 2);
        rs1 += __shfl_xor_sync(0xffffffffu, rs1, 1);
        rs1 += __shfl_xor_sync(0xffffffffu, rs1, 2);
        l0 = l0 * sc0 + rs0;
        l1 = l1 * sc1 + rs1;
#pragma unroll
        for (int nt = 0; nt < 8; nt++) {
            o[nt][0] *= sc0; o[nt][1] *= sc0;
            o[nt][2] *= sc1; o[nt][3] *= sc1;
        }

#pragma unroll
        for (int nt = 0; nt < 8; nt++) {
            if (nt < NTD) {
                const int ch = nt * 2 + (cq >> 1);
                const int of = (2 * cq) & 3;
                *(float2*)&Ps[rq * 64 + SWA(rq, ch) * 4 + of] =
                    make_float2(rtf(s[nt][0]), rtf(s[nt][1]));
                *(float2*)&Ps[(rq + 8) * 64 + SWA(rq + 8, ch) * 4 + of] =
                    make_float2(rtf(s[nt][2]), rtf(s[nt][3]));
            }
        }
        __syncwarp();

        // PV: only kpos chunks ks < NTD contribute (P beyond is masked-zero)
#pragma unroll
        for (int ks = 0; ks < 8; ks++) {
            if (ks < NTD) {
                const int chunk = ks * 2 + (sub >> 1);
                unsigned ap[4];
                ldsm4(ap, Ps + rowA * 64 + SWA(rowA, chunk) * 4);
#pragma unroll
                for (int p = 0; p < 4; p++) {
                    const int rv = p * 16 + (sub & 1) * 8 + rl;
                    unsigned bv[4];
                    ldsm4(bv, Vb + rv * 64 + SWA(rv, chunk) * 4);
                    mma_tf32(o[2 * p],     ap, bv[0], bv[2]);
                    mma_tf32(o[2 * p + 1], ap, bv[1], bv[3]);
                }
            }
        }
    }

    const int b = bh >> 4;
    const int h = bh & 15;
    const float inv0 = 1.0f / l0;
    const float inv1 = 1.0f / l1;
    float* Og = g_att + ((size_t)(b * NT + q0 + rq)) * NC + (h << 6);
#pragma unroll
    for (int nt = 0; nt < 8; nt++) {
        int col = nt * 8 + 2 * cq;
        *(float2*)(Og + col) =
            make_float2(rtf(o[nt][0] * inv0), rtf(o[nt][1] * inv0));
        *(float2*)(Og + (size_t)8 * NC + col) =
            make_float2(rtf(o[nt][2] * inv1), rtf(o[nt][3] * inv1));
    }
}

// ---------------------------------------------------------------------------
// launch
// ---------------------------------------------------------------------------
extern "C" void kernel_launch(void* const* d_in, const int* in_sizes, int n_in,
                              void* d_out, int out_size)
{
    const float* x     = (const float*)d_in[0];
    const float* Wqkv  = (const float*)d_in[1];
    const float* Wproj = (const float*)d_in[2];
    float* out = (float*)d_out;

    void *px, *pwqkv, *pwproj, *patt;
    cudaGetSymbolAddress(&px, g_x);
    cudaGetSymbolAddress(&pwqkv, g_wqkv);
    cudaGetSymbolAddress(&pwproj, g_wproj);
    cudaGetSymbolAddress(&patt, g_att);

    cudaFuncSetAttribute(gemm_tc<1>,
                         cudaFuncAttributeMaxDynamicSharedMemorySize, GEMM_SMEM);
    cudaFuncSetAttribute(gemm_tc<0>,
                         cudaFuncAttributeMaxDynamicSharedMemorySize, GEMM_SMEM);
    cudaFuncSetAttribute(attn_tc,
                         cudaFuncAttributeMaxDynamicSharedMemorySize, ATTN_SMEM);

    // 0) pre-round x; round+transpose weights to [n][k]
    cvt_kernel<<<(NM * NC / 4 + 255) / 256, 256>>>(
        (const float4*)x, (uint4*)px, NM * NC / 4);
    cvt_t_kernel<<<dim3(3 * NC / 32, NC / 32), 256>>>(
        Wqkv, (float*)pwqkv, NC, 3 * NC);
    cvt_t_kernel<<<dim3(NC / 32, NC / 32), 256>>>(
        Wproj, (float*)pwproj, NC, NC);

    // 1) qkv = x @ Wqkv -> scatter q,k [bh][t][d], v [bh][d][t]
    gemm_tc<1><<<dim3(3 * NC / BN, NM / BM), 128, GEMM_SMEM>>>(
        (const float*)px, (const float*)pwqkv, nullptr, NM, 3 * NC, NC);

    // 2) causal attention -> g_att (rounded)
    attn_tc<<<dim3(NT / 64, NBH), 128, ATTN_SMEM>>>();

    // 3) out = g_att @ Wproj
    gemm_tc<0><<<dim3(NC / BN, NM / BM), 128, GEMM_SMEM>>>(
        (const float*)patt, (const float*)pwproj, out, NM, NC, NC);
}

// round 13
// speedup vs baseline: 1.0488x; 1.0097x over previous
#include <cuda_runtime.h>

// ---------------------------------------------------------------------------
// B=4, T=2048, C=1024, H=16, D=64.  All matmuls: mma.sync.m16n8k8.tf32.
// ldmatrix fragments, cp.async pipelines.
// GEMM: 128x128x32 tile, 4 warps (64x64 warp tile), 3 stages, 2 CTAs/SM.
//   gemm1 reads raw x and rounds A-fragments in registers (CVT_A=1);
//   weights pre-rounded+transposed; gemm2's A (g_att) pre-rounded by attn.
// Attention: exact Round-10 structure (64-q blocks, 2 CTAs/SM, Q frags
//   hoisted, diagonal specialized, reversed launch order).
// ---------------------------------------------------------------------------

#define NBH 64
#define NT  2048
#define ND  64
#define NC  1024
#define NM  8192

__device__ float g_q[NBH * NT * ND];
__device__ float g_k[NBH * NT * ND];
__device__ float g_v[NBH * NT * ND];        // transposed: [bh][d][t]
__device__ float g_att[NM * NC];
__device__ float g_wqkv[3 * NC * NC];       // transposed: [n][k]
__device__ float g_wproj[NC * NC];          // transposed: [n][k]

__device__ __forceinline__ unsigned f2tf(float f) {
    unsigned u;
    asm("cvt.rna.tf32.f32 %0, %1;" : "=r"(u) : "f"(f));
    return u;
}
__device__ __forceinline__ float rtf(float x) { return __uint_as_float(f2tf(x)); }
__device__ __forceinline__ unsigned rtfu(unsigned x) {
    return f2tf(__uint_as_float(x));
}

__device__ __forceinline__ void mma_tf32(float* c, const unsigned* a,
                                         unsigned b0, unsigned b1) {
    asm volatile(
        "mma.sync.aligned.m16n8k8.row.col.f32.tf32.tf32.f32 "
        "{%0,%1,%2,%3}, {%4,%5,%6,%7}, {%8,%9}, {%0,%1,%2,%3};"
        : "+f"(c[0]), "+f"(c[1]), "+f"(c[2]), "+f"(c[3])
        : "r"(a[0]), "r"(a[1]), "r"(a[2]), "r"(a[3]), "r"(b0), "r"(b1));
}

__device__ __forceinline__ void ldsm4(unsigned* r, const float* p) {
    unsigned a = (unsigned)__cvta_generic_to_shared(p);
    asm volatile("ldmatrix.sync.aligned.m8n8.x4.shared.b16 {%0,%1,%2,%3}, [%4];"
                 : "=r"(r[0]), "=r"(r[1]), "=r"(r[2]), "=r"(r[3]) : "r"(a));
}

__device__ __forceinline__ void cp16(void* smem_dst, const void* gmem_src) {
    unsigned sa = (unsigned)__cvta_generic_to_shared(smem_dst);
    asm volatile("cp.async.cg.shared.global [%0], [%1], 16;" :: "r"(sa), "l"(gmem_src));
}
#define CPCOMMIT() asm volatile("cp.async.commit_group;")

__device__ __forceinline__ float fexp2(float x) {
    float y;
    asm("ex2.approx.f32 %0, %1;" : "=f"(y) : "f"(x));
    return y;
}

// swizzles (chunk = 4-float group within a row)
#define SWB(r, c) ((c) ^ ((r) & 7))          // rows of 32 floats (GEMM BK=32)
#define SWA(r, c) ((c) ^ ((r) & 7))          // rows of 64 floats (attention)

// ---------------------------------------------------------------------------
// weight pre-round + transpose: W[K][N] -> Wt[N][K]
// ---------------------------------------------------------------------------
__global__ void cvt_t_kernel(const float* __restrict__ src,
                             float* __restrict__ dst, int K, int N)
{
    __shared__ float t[32][33];
    const int n0 = blockIdx.x << 5;
    const int k0 = blockIdx.y << 5;
    const int tx = threadIdx.x & 31;
    const int ty = threadIdx.x >> 5;   // 0..7
#pragma unroll
    for (int j = 0; j < 4; j++)
        t[ty + j * 8][tx] = src[(size_t)(k0 + ty + j * 8) * N + n0 + tx];
    __syncthreads();
#pragma unroll
    for (int j = 0; j < 4; j++)
        dst[(size_t)(n0 + ty + j * 8) * K + k0 + tx] = rtf(t[tx][ty + j * 8]);
}

// ---------------------------------------------------------------------------
// GEMM: 128m x 128n x 32k tile, 128 threads (4 warps 2x2, warp tile 64x64),
// 3-stage cp.async, 2 CTAs/SM.
// CVT_A=1: round A fragments (raw fp32 A input).  SCATTER=1: QKV scatter.
// ---------------------------------------------------------------------------
#define BM 128
#define BN 128
#define BK 32
#define STG 3
#define ASZ (BM * BK)
#define BSZ (BN * BK)
#define GEMM_SMEM (STG * (ASZ + BSZ) * 4)   // 98304 B

template <int SCATTER, int CVT_A>
__global__ void __launch_bounds__(128, 2) gemm_tc(
    const float* __restrict__ A, const float* __restrict__ Bt,
    float* __restrict__ C, int M, int N, int K)
{
    extern __shared__ float sh[];
    float* As = sh;
    float* Bs = sh + STG * ASZ;

    const int tid  = threadIdx.x;
    const int lane = tid & 31;
    const int w    = tid >> 5;        // 0..3
    const int wm   = w >> 1;          // 0..1 -> m*64
    const int wn   = w & 1;           // 0..1 -> n*64
    const int g    = lane >> 2;
    const int cq   = lane & 3;
    const int sub  = lane >> 3;       // 0..3 (ldmatrix sub-matrix)
    const int rl   = lane & 7;
    const int bm   = blockIdx.y << 7;
    const int bn   = blockIdx.x << 7;

    const int NIT = K >> 5;

    auto load_tile = [&](int kt, int s) {
        const float* Ag = A + (size_t)bm * K + kt * BK;
#pragma unroll
        for (int i = 0; i < 8; i++) {
            int idx = tid + i * 128;
            int r = idx >> 3, c = idx & 7;
            cp16(&As[s * ASZ + r * 32 + SWB(r, c) * 4], Ag + (size_t)r * K + c * 4);
        }
        const float* Bg = Bt + (size_t)bn * K + kt * BK;
#pragma unroll
        for (int i = 0; i < 8; i++) {
            int idx = tid + i * 128;
            int r = idx >> 3, c = idx & 7;
            cp16(&Bs[s * BSZ + r * 32 + SWB(r, c) * 4], Bg + (size_t)r * K + c * 4);
        }
    };

    float acc[4][8][4];
#pragma unroll
    for (int mi = 0; mi < 4; mi++)
#pragma unroll
        for (int ni = 0; ni < 8; ni++)
#pragma unroll
            for (int r = 0; r < 4; r++) acc[mi][ni][r] = 0.0f;

    load_tile(0, 0); CPCOMMIT();
    load_tile(1, 1); CPCOMMIT();

    int s_cur = 0, s_nxt = 2;
#pragma unroll 1
    for (int kt = 0; kt < NIT; kt++) {
        asm volatile("cp.async.wait_group 1;");
        __syncthreads();

        const float* Asb = As + s_cur * ASZ;
        const float* Bsb = Bs + s_cur * BSZ;
        const int s_pf = s_nxt;
        s_nxt = s_cur;
        s_cur = (s_cur == 2) ? 0 : s_cur + 1;

        auto do_chunk = [&](int ks) {
            const int chunk = ks * 2 + (sub >> 1);
            unsigned af[4][4], bf[4][4];
#pragma unroll
            for (int mi = 0; mi < 4; mi++) {
                const int row = wm * 64 + mi * 16 + (sub & 1) * 8 + rl;
                ldsm4(af[mi], Asb + row * 32 + SWB(row, chunk) * 4);
                if (CVT_A) {
#pragma unroll
                    for (int r = 0; r < 4; r++) af[mi][r] = rtfu(af[mi][r]);
                }
            }
#pragma unroll
            for (int p = 0; p < 4; p++) {
                const int row = wn * 64 + p * 16 + (sub & 1) * 8 + rl;
                ldsm4(bf[p], Bsb + row * 32 + SWB(row, chunk) * 4);
            }
#pragma unroll
            for (int mi = 0; mi < 4; mi++)
#pragma unroll
                for (int p = 0; p < 4; p++) {
                    mma_tf32(acc[mi][2 * p],     af[mi], bf[p][0], bf[p][2]);
                    mma_tf32(acc[mi][2 * p + 1], af[mi], bf[p][1], bf[p][3]);
                }
        };

        do_chunk(0);
        if (kt + 2 < NIT) load_tile(kt + 2, s_pf);
        CPCOMMIT();
#pragma unroll
        for (int ks = 1; ks < 4; ks++) do_chunk(ks);
    }

    // epilogue
#pragma unroll
    for (int mi = 0; mi < 4; mi++) {
        const int row = bm + wm * 64 + mi * 16 + g;
#pragma unroll
        for (int ni = 0; ni < 8; ni++) {
            const int col = bn + wn * 64 + ni * 8 + 2 * cq;
            if (SCATTER) {
                const int which = col >> 10;
                const int h     = (col & 1023) >> 6;
                const int d0    = col & 63;
                const int b     = row >> 11, t = row & 2047;
                if (which == 2) {
                    float* p = g_v + ((size_t)((b * 16 + h) * 64 + d0) << 11) + t;
                    p[0]            = rtf(acc[mi][ni][0]);
                    p[2048]         = rtf(acc[mi][ni][1]);
                    p[8]            = rtf(acc[mi][ni][2]);
                    p[2048 + 8]     = rtf(acc[mi][ni][3]);
                } else {
                    float* dst = (which == 0) ? g_q : g_k;
                    float* p = dst + ((size_t)((b * 16 + h) * 2048 + t) << 6) + d0;
                    *(float2*)p = make_float2(rtf(acc[mi][ni][0]), rtf(acc[mi][ni][1]));
                    *(float2*)(p + (8 << 6)) =
                        make_float2(rtf(acc[mi][ni][2]), rtf(acc[mi][ni][3]));
                }
            } else {
                *(float2*)&C[(size_t)row * N + col] =
                    make_float2(acc[mi][ni][0], acc[mi][ni][1]);
                *(float2*)&C[(size_t)(row + 8) * N + col] =
                    make_float2(acc[mi][ni][2], acc[mi][ni][3]);
            }
        }
    }
}

// ---------------------------------------------------------------------------
// Causal flash attention (exact Round-10): 128 threads = 4 warps, 64 q rows,
// 2 CTAs/SM. Q frags hoisted, diagonal specialized, reversed launch order.
// ---------------------------------------------------------------------------
#define AQ  (64 * 64)
#define AKV (64 * 64)
#define ATTN_SMEM ((AQ + 4 * AKV + 64 * 64) * 4)   // 98304 B
#define SCL 0.180336880f   // 0.125 * log2(e)

__global__ void __launch_bounds__(128, 2) attn_tc()
{
    extern __shared__ float sh[];
    float* Qs = sh;                    // [64][64]
    float* Ks = sh + AQ;               // [2][64][64]  (rows = kpos)
    float* Vs = sh + AQ + 2 * AKV;     // [2][64][64]  (rows = d)
    float* Ps = sh + AQ + 4 * AKV;     // [64][64]

    const int tid  = threadIdx.x;
    const int lane = tid & 31;
    const int w    = tid >> 5;         // 0..3
    const int g    = lane >> 2;
    const int cq   = lane & 3;
    const int sub  = lane >> 3;
    const int rl   = lane & 7;
    const int bh   = blockIdx.y;
    const int q0   = (gridDim.x - 1 - blockIdx.x) << 6;   // big tiles first

    const float* Qg  = g_q + ((size_t)bh * NT + q0) * ND;
    const float* Kg0 = g_k + (size_t)bh * NT * ND;
    const float* Vg0 = g_v + (size_t)bh * ND * NT;   // [d][t]

    auto load_kv = [&](int kt, int s) {
        const float* Kg = Kg0 + ((size_t)kt << 12);
        const float* Vg = Vg0 + (kt << 6);
#pragma unroll
        for (int i = 0; i < 8; i++) {
            int idx = tid + i * 128;
            int r = idx >> 4, c = idx & 15;
            cp16(&Ks[s * AKV + r * 64 + SWA(r, c) * 4], Kg + r * 64 + c * 4);
            cp16(&Vs[s * AKV + r * 64 + SWA(r, c) * 4], Vg + (size_t)r * NT + c * 4);
        }
    };

    // Q + KV(0) in group 0
#pragma unroll
    for (int i = 0; i < 8; i++) {
        int idx = tid + i * 128;
        int r = idx >> 4, c = idx & 15;
        cp16(&Qs[r * 64 + SWA(r, c) * 4], Qg + r * 64 + c * 4);
    }
    load_kv(0, 0);
    CPCOMMIT();
    asm volatile("cp.async.wait_group 0;");
    __syncthreads();

    const int rq    = w * 16 + g;
    const int rowA  = w * 16 + (sub & 1) * 8 + rl;   // ldmatrix A row
    const int ktmax = q0 >> 6;
    const int NTD   = 2 * w + 2;   // diag: kpos 8-tiles needed by this warp

    // hoist Q fragments (loop-invariant)
    unsigned qf[8][4];
#pragma unroll
    for (int ks = 0; ks < 8; ks++) {
        const int chunk = ks * 2 + (sub >> 1);
        ldsm4(qf[ks], Qs + rowA * 64 + SWA(rowA, chunk) * 4);
    }

    float m0 = -1e30f, m1 = -1e30f, l0 = 0.0f, l1 = 0.0f;
    float o[8][4];
#pragma unroll
    for (int nt = 0; nt < 8; nt++)
#pragma unroll
        for (int r = 0; r < 4; r++) o[nt][r] = 0.0f;

    // ---------------- main loop: non-diagonal tiles (no masking) ----------
    for (int kt = 0; kt < ktmax; kt++) {
        const float* Kb = Ks + (kt & 1) * AKV;
        const float* Vb = Vs + (kt & 1) * AKV;

        float s[8][4];
#pragma unroll
        for (int nt = 0; nt < 8; nt++)
#pragma unroll
            for (int r = 0; r < 4; r++) s[nt][r] = 0.0f;

        // S chunk ks=0, then issue next K/V prefetch, then chunks 1..7
        {
            const int chunk = (sub >> 1);
#pragma unroll
            for (int p = 0; p < 4; p++) {
                const int rk = p * 16 + (sub & 1) * 8 + rl;
                unsigned bk[4];
                ldsm4(bk, Kb + rk * 64 + SWA(rk, chunk) * 4);
                mma_tf32(s[2 * p],     qf[0], bk[0], bk[2]);
                mma_tf32(s[2 * p + 1], qf[0], bk[1], bk[3]);
            }
        }
        load_kv(kt + 1, (kt + 1) & 1);
        CPCOMMIT();
#pragma unroll
        for (int ks = 1; ks < 8; ks++) {
            const int chunk = ks * 2 + (sub >> 1);
#pragma unroll
            for (int p = 0; p < 4; p++) {
                const int rk = p * 16 + (sub & 1) * 8 + rl;
                unsigned bk[4];
                ldsm4(bk, Kb + rk * 64 + SWA(rk, chunk) * 4);
                mma_tf32(s[2 * p],     qf[ks], bk[0], bk[2]);
                mma_tf32(s[2 * p + 1], qf[ks], bk[1], bk[3]);
            }
        }

#pragma unroll
        for (int nt = 0; nt < 8; nt++)
#pragma unroll
            for (int r = 0; r < 4; r++) s[nt][r] *= SCL;

        // online softmax (log2 domain)
        float rm0 = -1e30f, rm1 = -1e30f;
#pragma unroll
        for (int nt = 0; nt < 8; nt++) {
            rm0 = fmaxf(rm0, fmaxf(s[nt][0], s[nt][1]));
            rm1 = fmaxf(rm1, fmaxf(s[nt][2], s[nt][3]));
        }
        rm0 = fmaxf(rm0, __shfl_xor_sync(0xffffffffu, rm0, 1));
        rm0 = fmaxf(rm0, __shfl_xor_sync(0xffffffffu, rm0, 2));
        rm1 = fmaxf(rm1, __shfl_xor_sync(0xffffffffu, rm1, 1));
        rm1 = fmaxf(rm1, __shfl_xor_sync(0xffffffffu, rm1, 2));

        float mn0 = fmaxf(m0, rm0), mn1 = fmaxf(m1, rm1);
        float sc0 = fexp2(m0 - mn0), sc1 = fexp2(m1 - mn1);
        float rs0 = 0.0f, rs1 = 0.0f;
#pragma unroll
        for (int nt = 0; nt < 8; nt++) {
            s[nt][0] = fexp2(s[nt][0] - mn0);
            s[nt][1] = fexp2(s[nt][1] - mn0);
            s[nt][2] = fexp2(s[nt][2] - mn1);
            s[nt][3] = fexp2(s[nt][3] - mn1);
            rs0 += s[nt][0] + s[nt][1];
            rs1 += s[nt][2] + s[nt][3];
        }
        rs0 += __shfl_xor_sync(0xffffffffu, rs0, 1);
        rs0 += __shfl_xor_sync(0xffffffffu, rs0, 2);
        rs1 += __shfl_xor_sync(0xffffffffu, rs1, 1);
        rs1 += __shfl_xor_sync(0xffffffffu, rs1, 2);
        l0 = l0 * sc0 + rs0;
        l1 = l1 * sc1 + rs1;
        m0 = mn0; m1 = mn1;
#pragma unroll
        for (int nt = 0; nt < 8; nt++) {
            o[nt][0] *= sc0; o[nt][1] *= sc0;
            o[nt][2] *= sc1; o[nt][3] *= sc1;
        }

        // P -> smem (warp-private rows), swizzled, rounded
#pragma unroll
        for (int nt = 0; nt < 8; nt++) {
            const int ch = nt * 2 + (cq >> 1);
            const int of = (2 * cq) & 3;
            *(float2*)&Ps[rq * 64 + SWA(rq, ch) * 4 + of] =
                make_float2(rtf(s[nt][0]), rtf(s[nt][1]));
            *(float2*)&Ps[(rq + 8) * 64 + SWA(rq + 8, ch) * 4 + of] =
                make_float2(rtf(s[nt][2]), rtf(s[nt][3]));
        }
        __syncwarp();

        // O += P V   (V is [d][t] in smem: rows = d)
#pragma unroll
        for (int ks = 0; ks < 8; ks++) {
            const int chunk = ks * 2 + (sub >> 1);
            unsigned ap[4];
            ldsm4(ap, Ps + rowA * 64 + SWA(rowA, chunk) * 4);
#pragma unroll
            for (int p = 0; p < 4; p++) {
                const int rv = p * 16 + (sub & 1) * 8 + rl;   // d row
                unsigned bv[4];
                ldsm4(bv, Vb + rv * 64 + SWA(rv, chunk) * 4);
                mma_tf32(o[2 * p],     ap, bv[0], bv[2]);
                mma_tf32(o[2 * p + 1], ap, bv[1], bv[3]);
            }
        }

        asm volatile("cp.async.wait_group 0;");
        __syncthreads();
    }

    // ---------------- diagonal tile (kt == ktmax), per-warp reduced range --
    {
        const float* Kb = Ks + (ktmax & 1) * AKV;
        const float* Vb = Vs + (ktmax & 1) * AKV;

        float s[8][4];
#pragma unroll
        for (int nt = 0; nt < 8; nt++)
#pragma unroll
            for (int r = 0; r < 4; r++) s[nt][r] = 0.0f;

        // S: only kpos tile-pairs p <= w needed (warp-uniform guard)
#pragma unroll
        for (int ks = 0; ks < 8; ks++) {
            const int chunk = ks * 2 + (sub >> 1);
#pragma unroll
            for (int p = 0; p < 4; p++) {
                if (p <= w) {
                    const int rk = p * 16 + (sub & 1) * 8 + rl;
                    unsigned bk[4];
                    ldsm4(bk, Kb + rk * 64 + SWA(rk, chunk) * 4);
                    mma_tf32(s[2 * p],     qf[ks], bk[0], bk[2]);
                    mma_tf32(s[2 * p + 1], qf[ks], bk[1], bk[3]);
                }
            }
        }

        // scale + causal mask (nt < NTD only)
        const int r0 = rq, r1 = rq + 8;
#pragma unroll
        for (int nt = 0; nt < 8; nt++) {
            if (nt < NTD) {
                int gc = nt * 8 + 2 * cq;
                s[nt][0] = (gc     <= r0) ? s[nt][0] * SCL : -1e30f;
                s[nt][1] = (gc + 1 <= r0) ? s[nt][1] * SCL : -1e30f;
                s[nt][2] = (gc     <= r1) ? s[nt][2] * SCL : -1e30f;
                s[nt][3] = (gc + 1 <= r1) ? s[nt][3] * SCL : -1e30f;
            }
        }

        float rm0 = -1e30f, rm1 = -1e30f;
#pragma unroll
        for (int nt = 0; nt < 8; nt++) {
            if (nt < NTD) {
                rm0 = fmaxf(rm0, fmaxf(s[nt][0], s[nt][1]));
                rm1 = fmaxf(rm1, fmaxf(s[nt][2], s[nt][3]));
            }
        }
        rm0 = fmaxf(rm0, __shfl_xor_sync(0xffffffffu, rm0, 1));
        rm0 = fmaxf(rm0, __shfl_xor_sync(0xffffffffu, rm0, 2));
        rm1 = fmaxf(rm1, __shfl_xor_sync(0xffffffffu, rm1, 1));
        rm1 = fmaxf(rm1, __shfl_xor_sync(0xffffffffu, rm1, 2));

        float mn0 = fmaxf(m0, rm0), mn1 = fmaxf(m1, rm1);
        float sc0 = fexp2(m0 - mn0), sc1 = fexp2(m1 - mn1);
        float rs0 = 0.0f, rs1 = 0.0f;
#pragma unroll
        for (int nt = 0; nt < 8; nt++) {
            if (nt < NTD) {
                s[nt][0] = fexp2(s[nt][0] - mn0);
                s[nt][1] = fexp2(s[nt][1] - mn0);
                s[nt][2] = fexp2(s[nt][2] - mn1);
                s[nt][3] = fexp2(s[nt][3] - mn1);
                rs0 += s[nt][0] + s[nt][1];
                rs1 += s[nt][2] + s[nt][3];
            }
        }
        rs0 += __shfl_xor_sync(0xffffffffu, rs0, 1);
        rs0 += __shfl_xor_sync(0xffffffffu, rs0, 2);
        rs1 += __shfl_xor_sync(0xffffffffu, rs1, 1);
        rs1 += __shfl_xor_sync(0xffffffffu, rs1, 2);
        l0 = l0 * sc0 + rs0;
        l1 = l1 * sc1 + rs1;
#pragma unroll
        for (int nt = 0; nt < 8; nt++) {
            o[nt][0] *= sc0; o[nt][1] *= sc0;
            o[nt][2] *= sc1; o[nt][3] *= sc1;
        }

#pragma unroll
        for (int nt = 0; nt < 8; nt++) {
            if (nt < NTD) {
                const int ch = nt * 2 + (cq >> 1);
                const int of = (2 * cq) & 3;
                *(float2*)&Ps[rq * 64 + SWA(rq, ch) * 4 + of] =
                    make_float2(rtf(s[nt][0]), rtf(s[nt][1]));
                *(float2*)&Ps[(rq + 8) * 64 + SWA(rq + 8, ch) * 4 + of] =
                    make_float2(rtf(s[nt][2]), rtf(s[nt][3]));
            }
        }
        __syncwarp();

        // PV: only kpos chunks ks < NTD contribute (P beyond is masked-zero)
#pragma unroll
        for (int ks = 0; ks < 8; ks++) {
            if (ks < NTD) {
                const int chunk = ks * 2 + (sub >> 1);
                unsigned ap[4];
                ldsm4(ap, Ps + rowA * 64 + SWA(rowA, chunk) * 4);
#pragma unroll
                for (int p = 0; p < 4; p++) {
                    const int rv = p * 16 + (sub & 1) * 8 + rl;
                    unsigned bv[4];
                    ldsm4(bv, Vb + rv * 64 + SWA(rv, chunk) * 4);
                    mma_tf32(o[2 * p],     ap, bv[0], bv[2]);
                    mma_tf32(o[2 * p + 1], ap, bv[1], bv[3]);
                }
            }
        }
    }

    const int b = bh >> 4;
    const int h = bh & 15;
    const float inv0 = 1.0f / l0;
    const float inv1 = 1.0f / l1;
    float* Og = g_att + ((size_t)(b * NT + q0 + rq)) * NC + (h << 6);
#pragma unroll
    for (int nt = 0; nt < 8; nt++) {
        int col = nt * 8 + 2 * cq;
        *(float2*)(Og + col) =
            make_float2(rtf(o[nt][0] * inv0), rtf(o[nt][1] * inv0));
        *(float2*)(Og + (size_t)8 * NC + col) =
            make_float2(rtf(o[nt][2] * inv1), rtf(o[nt][3] * inv1));
    }
}

// ---------------------------------------------------------------------------
// launch
// ---------------------------------------------------------------------------
extern "C" void kernel_launch(void* const* d_in, const int* in_sizes, int n_in,
                              void* d_out, int out_size)
{
    const float* x     = (const float*)d_in[0];
    const float* Wqkv  = (const float*)d_in[1];
    const float* Wproj = (const float*)d_in[2];
    float* out = (float*)d_out;

    void *pwqkv, *pwproj, *patt;
    cudaGetSymbolAddress(&pwqkv, g_wqkv);
    cudaGetSymbolAddress(&pwproj, g_wproj);
    cudaGetSymbolAddress(&patt, g_att);

    cudaFuncSetAttribute((const void*)gemm_tc<1, 1>,
                         cudaFuncAttributeMaxDynamicSharedMemorySize, GEMM_SMEM);
    cudaFuncSetAttribute((const void*)gemm_tc<0, 0>,
                         cudaFuncAttributeMaxDynamicSharedMemorySize, GEMM_SMEM);
    cudaFuncSetAttribute((const void*)attn_tc,
                         cudaFuncAttributeMaxDynamicSharedMemorySize, ATTN_SMEM);

    // 0) round+transpose weights to [n][k]  (x is read raw by gemm1)
    cvt_t_kernel<<<dim3(3 * NC / 32, NC / 32), 256>>>(
        Wqkv, (float*)pwqkv, NC, 3 * NC);
    cvt_t_kernel<<<dim3(NC / 32, NC / 32), 256>>>(
        Wproj, (float*)pwproj, NC, NC);

    // 1) qkv = x @ Wqkv -> scatter q,k [bh][t][d], v [bh][d][t]
    gemm_tc<1, 1><<<dim3(3 * NC / BN, NM / BM), 128, GEMM_SMEM>>>(
        x, (const float*)pwqkv, nullptr, NM, 3 * NC, NC);

    // 2) causal attention -> g_att (rounded)
    attn_tc<<<dim3(NT / 64, NBH), 128, ATTN_SMEM>>>();

    // 3) out = g_att @ Wproj
    gemm_tc<0, 0><<<dim3(NC / BN, NM / BM), 128, GEMM_SMEM>>>(
        (const float*)patt, (const float*)pwproj, out, NM, NC, NC);
}

// round 14
// speedup vs baseline: 1.0601x; 1.0108x over previous
#include <cuda_runtime.h>

// ---------------------------------------------------------------------------
// B=4, T=2048, C=1024, H=16, D=64.  All matmuls: mma.sync.m16n8k8.tf32.
// ldmatrix fragments, cp.async pipelines, pre-rounded tf32 inputs.
// GEMM: 128x128x32 tile, 4 warps (64x64 warp tile), 3 stages, 2 CTAs/SM
//       (exact Round-10 structure).
// Attention: 64-q blocks, 2 CTAs/SM, Q frags hoisted, SOFTWARE-PIPELINED:
//       softmax(kt) | wait KV | S(kt+1)+PV(kt) merged MMA burst | prefetch.
// ---------------------------------------------------------------------------

#define NBH 64
#define NT  2048
#define ND  64
#define NC  1024
#define NM  8192

__device__ float g_q[NBH * NT * ND];
__device__ float g_k[NBH * NT * ND];
__device__ float g_v[NBH * NT * ND];        // transposed: [bh][d][t]
__device__ float g_att[NM * NC];
__device__ float g_x[NM * NC];
__device__ float g_wqkv[3 * NC * NC];       // transposed: [n][k]
__device__ float g_wproj[NC * NC];          // transposed: [n][k]

__device__ __forceinline__ unsigned f2tf(float f) {
    unsigned u;
    asm("cvt.rna.tf32.f32 %0, %1;" : "=r"(u) : "f"(f));
    return u;
}
__device__ __forceinline__ float rtf(float x) { return __uint_as_float(f2tf(x)); }

__device__ __forceinline__ void mma_tf32(float* c, const unsigned* a,
                                         unsigned b0, unsigned b1) {
    asm volatile(
        "mma.sync.aligned.m16n8k8.row.col.f32.tf32.tf32.f32 "
        "{%0,%1,%2,%3}, {%4,%5,%6,%7}, {%8,%9}, {%0,%1,%2,%3};"
        : "+f"(c[0]), "+f"(c[1]), "+f"(c[2]), "+f"(c[3])
        : "r"(a[0]), "r"(a[1]), "r"(a[2]), "r"(a[3]), "r"(b0), "r"(b1));
}

__device__ __forceinline__ void ldsm4(unsigned* r, const float* p) {
    unsigned a = (unsigned)__cvta_generic_to_shared(p);
    asm volatile("ldmatrix.sync.aligned.m8n8.x4.shared.b16 {%0,%1,%2,%3}, [%4];"
                 : "=r"(r[0]), "=r"(r[1]), "=r"(r[2]), "=r"(r[3]) : "r"(a));
}

__device__ __forceinline__ void cp16(void* smem_dst, const void* gmem_src) {
    unsigned sa = (unsigned)__cvta_generic_to_shared(smem_dst);
    asm volatile("cp.async.cg.shared.global [%0], [%1], 16;" :: "r"(sa), "l"(gmem_src));
}
#define CPCOMMIT() asm volatile("cp.async.commit_group;")

__device__ __forceinline__ float fexp2(float x) {
    float y;
    asm("ex2.approx.f32 %0, %1;" : "=f"(y) : "f"(x));
    return y;
}

// swizzles (chunk = 4-float group within a row)
#define SWB(r, c) ((c) ^ ((r) & 7))          // rows of 32 floats (GEMM BK=32)
#define SWA(r, c) ((c) ^ ((r) & 7))          // rows of 64 floats (attention)

// ---------------------------------------------------------------------------
// pre-round kernels
// ---------------------------------------------------------------------------
__global__ void cvt_kernel(const float4* __restrict__ src,
                           uint4* __restrict__ dst, int n4)
{
    int i = blockIdx.x * 256 + threadIdx.x;
    if (i < n4) {
        float4 v = src[i];
        uint4 u;
        u.x = f2tf(v.x); u.y = f2tf(v.y); u.z = f2tf(v.z); u.w = f2tf(v.w);
        dst[i] = u;
    }
}

// round + transpose W[K][N] -> Wt[N][K]
__global__ void cvt_t_kernel(const float* __restrict__ src,
                             float* __restrict__ dst, int K, int N)
{
    __shared__ float t[32][33];
    const int n0 = blockIdx.x << 5;
    const int k0 = blockIdx.y << 5;
    const int tx = threadIdx.x & 31;
    const int ty = threadIdx.x >> 5;   // 0..7
#pragma unroll
    for (int j = 0; j < 4; j++)
        t[ty + j * 8][tx] = src[(size_t)(k0 + ty + j * 8) * N + n0 + tx];
    __syncthreads();
#pragma unroll
    for (int j = 0; j < 4; j++)
        dst[(size_t)(n0 + ty + j * 8) * K + k0 + tx] = rtf(t[tx][ty + j * 8]);
}

// ---------------------------------------------------------------------------
// GEMM: exact Round-10 (128x128x32, 4 warps 2x2 / 64x64, 3-stage, 2 CTAs/SM).
// SCATTER=1: round + scatter q/k into [bh][t][d], v into [bh][d][t].
// ---------------------------------------------------------------------------
#define BM 128
#define BN 128
#define BK 32
#define STG 3
#define ASZ (BM * BK)
#define BSZ (BN * BK)
#define GEMM_SMEM (STG * (ASZ + BSZ) * 4)   // 98304 B

template <int SCATTER>
__global__ void __launch_bounds__(128, 2) gemm_tc(
    const float* __restrict__ A, const float* __restrict__ Bt,
    float* __restrict__ C, int M, int N, int K)
{
    extern __shared__ float sh[];
    float* As = sh;
    float* Bs = sh + STG * ASZ;

    const int tid  = threadIdx.x;
    const int lane = tid & 31;
    const int w    = tid >> 5;        // 0..3
    const int wm   = w >> 1;          // 0..1 -> m*64
    const int wn   = w & 1;           // 0..1 -> n*64
    const int g    = lane >> 2;
    const int cq   = lane & 3;
    const int sub  = lane >> 3;       // 0..3 (ldmatrix sub-matrix)
    const int rl   = lane & 7;
    const int bm   = blockIdx.y << 7;
    const int bn   = blockIdx.x << 7;

    const int NIT = K >> 5;

    auto load_tile = [&](int kt, int s) {
        const float* Ag = A + (size_t)bm * K + kt * BK;
#pragma unroll
        for (int i = 0; i < 8; i++) {
            int idx = tid + i * 128;
            int r = idx >> 3, c = idx & 7;
            cp16(&As[s * ASZ + r * 32 + SWB(r, c) * 4], Ag + (size_t)r * K + c * 4);
        }
        const float* Bg = Bt + (size_t)bn * K + kt * BK;
#pragma unroll
        for (int i = 0; i < 8; i++) {
            int idx = tid + i * 128;
            int r = idx >> 3, c = idx & 7;
            cp16(&Bs[s * BSZ + r * 32 + SWB(r, c) * 4], Bg + (size_t)r * K + c * 4);
        }
    };

    float acc[4][8][4];
#pragma unroll
    for (int mi = 0; mi < 4; mi++)
#pragma unroll
        for (int ni = 0; ni < 8; ni++)
#pragma unroll
            for (int r = 0; r < 4; r++) acc[mi][ni][r] = 0.0f;

    load_tile(0, 0); CPCOMMIT();
    load_tile(1, 1); CPCOMMIT();

    int s_cur = 0, s_nxt = 2;
#pragma unroll 1
    for (int kt = 0; kt < NIT; kt++) {
        asm volatile("cp.async.wait_group 1;");
        __syncthreads();

        const float* Asb = As + s_cur * ASZ;
        const float* Bsb = Bs + s_cur * BSZ;
        const int s_pf = s_nxt;
        s_nxt = s_cur;
        s_cur = (s_cur == 2) ? 0 : s_cur + 1;

        auto do_chunk = [&](int ks) {
            const int chunk = ks * 2 + (sub >> 1);
            unsigned af[4][4], bf[4][4];
#pragma unroll
            for (int mi = 0; mi < 4; mi++) {
                const int row = wm * 64 + mi * 16 + (sub & 1) * 8 + rl;
                ldsm4(af[mi], Asb + row * 32 + SWB(row, chunk) * 4);
            }
#pragma unroll
            for (int p = 0; p < 4; p++) {
                const int row = wn * 64 + p * 16 + (sub & 1) * 8 + rl;
                ldsm4(bf[p], Bsb + row * 32 + SWB(row, chunk) * 4);
            }
#pragma unroll
            for (int mi = 0; mi < 4; mi++)
#pragma unroll
                for (int p = 0; p < 4; p++) {
                    mma_tf32(acc[mi][2 * p],     af[mi], bf[p][0], bf[p][2]);
                    mma_tf32(acc[mi][2 * p + 1], af[mi], bf[p][1], bf[p][3]);
                }
        };

        do_chunk(0);
        if (kt + 2 < NIT) load_tile(kt + 2, s_pf);
        CPCOMMIT();
#pragma unroll
        for (int ks = 1; ks < 4; ks++) do_chunk(ks);
    }

    // epilogue
#pragma unroll
    for (int mi = 0; mi < 4; mi++) {
        const int row = bm + wm * 64 + mi * 16 + g;
#pragma unroll
        for (int ni = 0; ni < 8; ni++) {
            const int col = bn + wn * 64 + ni * 8 + 2 * cq;
            if (SCATTER) {
                const int which = col >> 10;
                const int h     = (col & 1023) >> 6;
                const int d0    = col & 63;
                const int b     = row >> 11, t = row & 2047;
                if (which == 2) {
                    float* p = g_v + ((size_t)((b * 16 + h) * 64 + d0) << 11) + t;
                    p[0]            = rtf(acc[mi][ni][0]);
                    p[2048]         = rtf(acc[mi][ni][1]);
                    p[8]            = rtf(acc[mi][ni][2]);
                    p[2048 + 8]     = rtf(acc[mi][ni][3]);
                } else {
                    float* dst = (which == 0) ? g_q : g_k;
                    float* p = dst + ((size_t)((b * 16 + h) * 2048 + t) << 6) + d0;
                    *(float2*)p = make_float2(rtf(acc[mi][ni][0]), rtf(acc[mi][ni][1]));
                    *(float2*)(p + (8 << 6)) =
                        make_float2(rtf(acc[mi][ni][2]), rtf(acc[mi][ni][3]));
                }
            } else {
                *(float2*)&C[(size_t)row * N + col] =
                    make_float2(acc[mi][ni][0], acc[mi][ni][1]);
                *(float2*)&C[(size_t)(row + 8) * N + col] =
                    make_float2(acc[mi][ni][2], acc[mi][ni][3]);
            }
        }
    }
}

// ---------------------------------------------------------------------------
// Causal flash attention, software-pipelined: 128 threads = 4 warps,
// 64 q rows/block, 2 CTAs/SM, reversed launch order.
// Per iteration: softmax(kt) -> Pstore -> [wait KV(kt+1)] ->
//   S(kt+1) + PV(kt) merged MMA burst -> sync -> prefetch KV(kt+2).
// Diagonal softmax/PV specialized per-warp in the epilogue.
// ---------------------------------------------------------------------------
#define AQ  (64 * 64)
#define AKV (64 * 64)
#define ATTN_SMEM ((AQ + 4 * AKV + 64 * 64) * 4)   // 98304 B
#define SCL 0.180336880f   // 0.125 * log2(e)

__global__ void __launch_bounds__(128, 2) attn_tc()
{
    extern __shared__ float sh[];
    float* Qs = sh;                    // [64][64]
    float* Ks = sh + AQ;               // [2][64][64]  (rows = kpos)
    float* Vs = sh + AQ + 2 * AKV;     // [2][64][64]  (rows = d)
    float* Ps = sh + AQ + 4 * AKV;     // [64][64]

    const int tid  = threadIdx.x;
    const int lane = tid & 31;
    const int w    = tid >> 5;         // 0..3
    const int g    = lane >> 2;
    const int cq   = lane & 3;
    const int sub  = lane >> 3;
    const int rl   = lane & 7;
    const int bh   = blockIdx.y;
    const int q0   = (gridDim.x - 1 - blockIdx.x) << 6;   // big tiles first

    const float* Qg  = g_q + ((size_t)bh * NT + q0) * ND;
    const float* Kg0 = g_k + (size_t)bh * NT * ND;
    const float* Vg0 = g_v + (size_t)bh * ND * NT;   // [d][t]

    auto load_kv = [&](int kt, int s) {
        const float* Kg = Kg0 + ((size_t)kt << 12);
        const float* Vg = Vg0 + (kt << 6);
#pragma unroll
        for (int i = 0; i < 8; i++) {
            int idx = tid + i * 128;
            int r = idx >> 4, c = idx & 15;
            cp16(&Ks[s * AKV + r * 64 + SWA(r, c) * 4], Kg + r * 64 + c * 4);
            cp16(&Vs[s * AKV + r * 64 + SWA(r, c) * 4], Vg + (size_t)r * NT + c * 4);
        }
    };

    // Q + KV(0) in group 0
#pragma unroll
    for (int i = 0; i < 8; i++) {
        int idx = tid + i * 128;
        int r = idx >> 4, c = idx & 15;
        cp16(&Qs[r * 64 + SWA(r, c) * 4], Qg + r * 64 + c * 4);
    }
    load_kv(0, 0);
    CPCOMMIT();
    asm volatile("cp.async.wait_group 0;");
    __syncthreads();

    const int rq    = w * 16 + g;
    const int rowA  = w * 16 + (sub & 1) * 8 + rl;   // ldmatrix A row
    const int ktmax = q0 >> 6;
    const int NTD   = 2 * w + 2;   // diag: kpos 8-tiles needed by this warp

    // hoist Q fragments (loop-invariant)
    unsigned qf[8][4];
#pragma unroll
    for (int ks = 0; ks < 8; ks++) {
        const int chunk = ks * 2 + (sub >> 1);
        ldsm4(qf[ks], Qs + rowA * 64 + SWA(rowA, chunk) * 4);
    }

    float m0 = -1e30f, m1 = -1e30f, l0 = 0.0f, l1 = 0.0f;
    float o[8][4];
#pragma unroll
    for (int nt = 0; nt < 8; nt++)
#pragma unroll
        for (int r = 0; r < 4; r++) o[nt][r] = 0.0f;

    float s[8][4];

    // S = Q K^T for one resident K buffer (full tile)
    auto compute_S = [&](const float* Kb) {
#pragma unroll
        for (int nt = 0; nt < 8; nt++)
#pragma unroll
            for (int r = 0; r < 4; r++) s[nt][r] = 0.0f;
#pragma unroll
        for (int ks = 0; ks < 8; ks++) {
            const int chunk = ks * 2 + (sub >> 1);
#pragma unroll
            for (int p = 0; p < 4; p++) {
                const int rk = p * 16 + (sub & 1) * 8 + rl;
                unsigned bk[4];
                ldsm4(bk, Kb + rk * 64 + SWA(rk, chunk) * 4);
                mma_tf32(s[2 * p],     qf[ks], bk[0], bk[2]);
                mma_tf32(s[2 * p + 1], qf[ks], bk[1], bk[3]);
            }
        }
    };

    // O += P V for one resident V buffer (full tile)
    auto compute_PV = [&](const float* Vb) {
#pragma unroll
        for (int ks = 0; ks < 8; ks++) {
            const int chunk = ks * 2 + (sub >> 1);
            unsigned ap[4];
            ldsm4(ap, Ps + rowA * 64 + SWA(rowA, chunk) * 4);
#pragma unroll
            for (int p = 0; p < 4; p++) {
                const int rv = p * 16 + (sub & 1) * 8 + rl;   // d row
                unsigned bv[4];
                ldsm4(bv, Vb + rv * 64 + SWA(rv, chunk) * 4);
                mma_tf32(o[2 * p],     ap, bv[0], bv[2]);
                mma_tf32(o[2 * p + 1], ap, bv[1], bv[3]);
            }
        }
    };

    // prologue: S(0); issue KV(1)
    compute_S(Ks);
    if (ktmax >= 1) { load_kv(1, 1); CPCOMMIT(); }

    // ---------------- pipelined main loop over unmasked tiles -------------
    for (int kt = 0; kt < ktmax; kt++) {
        // softmax(kt) — overlaps in-flight KV(kt+1) load
#pragma unroll
        for (int nt = 0; nt < 8; nt++)
#pragma unroll
            for (int r = 0; r < 4; r++) s[nt][r] *= SCL;

        float rm0 = -1e30f, rm1 = -1e30f;
#pragma unroll
        for (int nt = 0; nt < 8; nt++) {
            rm0 = fmaxf(rm0, fmaxf(s[nt][0], s[nt][1]));
            rm1 = fmaxf(rm1, fmaxf(s[nt][2], s[nt][3]));
        }
        rm0 = fmaxf(rm0, __shfl_xor_sync(0xffffffffu, rm0, 1));
        rm0 = fmaxf(rm0, __shfl_xor_sync(0xffffffffu, rm0, 2));
        rm1 = fmaxf(rm1, __shfl_xor_sync(0xffffffffu, rm1, 1));
        rm1 = fmaxf(rm1, __shfl_xor_sync(0xffffffffu, rm1, 2));

        float mn0 = fmaxf(m0, rm0), mn1 = fmaxf(m1, rm1);
        float sc0 = fexp2(m0 - mn0), sc1 = fexp2(m1 - mn1);
        float rs0 = 0.0f, rs1 = 0.0f;
#pragma unroll
        for (int nt = 0; nt < 8; nt++) {
            s[nt][0] = fexp2(s[nt][0] - mn0);
            s[nt][1] = fexp2(s[nt][1] - mn0);
            s[nt][2] = fexp2(s[nt][2] - mn1);
            s[nt][3] = fexp2(s[nt][3] - mn1);
            rs0 += s[nt][0] + s[nt][1];
            rs1 += s[nt][2] + s[nt][3];
        }
        rs0 += __shfl_xor_sync(0xffffffffu, rs0, 1);
        rs0 += __shfl_xor_sync(0xffffffffu, rs0, 2);
        rs1 += __shfl_xor_sync(0xffffffffu, rs1, 1);
        rs1 += __shfl_xor_sync(0xffffffffu, rs1, 2);
        l0 = l0 * sc0 + rs0;
        l1 = l1 * sc1 + rs1;
        m0 = mn0; m1 = mn1;
#pragma unroll
        for (int nt = 0; nt < 8; nt++) {
            o[nt][0] *= sc0; o[nt][1] *= sc0;
            o[nt][2] *= sc1; o[nt][3] *= sc1;
        }

        // P -> smem (warp-private rows), swizzled, rounded
#pragma unroll
        for (int nt = 0; nt < 8; nt++) {
            const int ch = nt * 2 + (cq >> 1);
            const int of = (2 * cq) & 3;
            *(float2*)&Ps[rq * 64 + SWA(rq, ch) * 4 + of] =
                make_float2(rtf(s[nt][0]), rtf(s[nt][1]));
            *(float2*)&Ps[(rq + 8) * 64 + SWA(rq + 8, ch) * 4 + of] =
                make_float2(rtf(s[nt][2]), rtf(s[nt][3]));
        }
        __syncwarp();

        // KV(kt+1) visible to all
        asm volatile("cp.async.wait_group 0;");
        __syncthreads();

        // merged MMA burst: S(kt+1) then PV(kt)
        compute_S(Ks + ((kt + 1) & 1) * AKV);
        compute_PV(Vs + (kt & 1) * AKV);

        // all warps done with V(kt) -> safe to overwrite buffer (kt+2)&1
        __syncthreads();
        if (kt + 2 <= ktmax) { load_kv(kt + 2, (kt + 2) & 1); CPCOMMIT(); }
    }

    // ---------------- diagonal tile (s holds S(ktmax)), per-warp range ----
    {
        const float* Vb = Vs + (ktmax & 1) * AKV;

        // scale + causal mask (nt < NTD only; beyond is fully masked/ignored)
        const int r0 = rq, r1 = rq + 8;
#pragma unroll
        for (int nt = 0; nt < 8; nt++) {
            if (nt < NTD) {
                int gc = nt * 8 + 2 * cq;
                s[nt][0] = (gc     <= r0) ? s[nt][0] * SCL : -1e30f;
                s[nt][1] = (gc + 1 <= r0) ? s[nt][1] * SCL : -1e30f;
                s[nt][2] = (gc     <= r1) ? s[nt][2] * SCL : -1e30f;
                s[nt][3] = (gc + 1 <= r1) ? s[nt][3] * SCL : -1e30f;
            }
        }

        float rm0 = -1e30f, rm1 = -1e30f;
#pragma unroll
        for (int nt = 0; nt < 8; nt++) {
            if (nt < NTD) {
                rm0 = fmaxf(rm0, fmaxf(s[nt][0], s[nt][1]));
                rm1 = fmaxf(rm1, fmaxf(s[nt][2], s[nt][3]));
            }
        }
        rm0 = fmaxf(rm0, __shfl_xor_sync(0xffffffffu, rm0, 1));
        rm0 = fmaxf(rm0, __shfl_xor_sync(0xffffffffu, rm0, 2));
        rm1 = fmaxf(rm1, __shfl_xor_sync(0xffffffffu, rm1, 1));
        rm1 = fmaxf(rm1, __shfl_xor_sync(0xffffffffu, rm1, 2));

        float mn0 = fmaxf(m0, rm0), mn1 = fmaxf(m1, rm1);
        float sc0 = fexp2(m0 - mn0), sc1 = fexp2(m1 - mn1);
        float rs0 = 0.0f, rs1 = 0.0f;
#pragma unroll
        for (int nt = 0; nt < 8; nt++) {
            if (nt < NTD) {
                s[nt][0] = fexp2(s[nt][0] - mn0);
                s[nt][1] = fexp2(s[nt][1] - mn0);
                s[nt][2] = fexp2(s[nt][2] - mn1);
                s[nt][3] = fexp2(s[nt][3] - mn1);
                rs0 += s[nt][0] + s[nt][1];
                rs1 += s[nt][2] + s[nt][3];
            }
        }
        rs0 += __shfl_xor_sync(0xffffffffu, rs0, 1);
        rs0 += __shfl_xor_sync(0xffffffffu, rs0, 2);
        rs1 += __shfl_xor_sync(0xffffffffu, rs1, 1);
        rs1 += __shfl_xor_sync(0xffffffffu, rs1, 2);
        l0 = l0 * sc0 + rs0;
        l1 = l1 * sc1 + rs1;
#pragma unroll
        for (int nt = 0; nt < 8; nt++) {
            o[nt][0] *= sc0; o[nt][1] *= sc0;
            o[nt][2] *= sc1; o[nt][3] *= sc1;
        }

#pragma unroll
        for (int nt = 0; nt < 8; nt++) {
            if (nt < NTD) {
                const int ch = nt * 2 + (cq >> 1);
                const int of = (2 * cq) & 3;
                *(float2*)&Ps[rq * 64 + SWA(rq, ch) * 4 + of] =
                    make_float2(rtf(s[nt][0]), rtf(s[nt][1]));
                *(float2*)&Ps[(rq + 8) * 64 + SWA(rq + 8, ch) * 4 + of] =
                    make_float2(rtf(s[nt][2]), rtf(s[nt][3]));
            }
        }
        __syncwarp();

        // PV: only kpos chunks ks < NTD contribute
#pragma unroll
        for (int ks = 0; ks < 8; ks++) {
            if (ks < NTD) {
                const int chunk = ks * 2 + (sub >> 1);
                unsigned ap[4];
                ldsm4(ap, Ps + rowA * 64 + SWA(rowA, chunk) * 4);
#pragma unroll
                for (int p = 0; p < 4; p++) {
                    const int rv = p * 16 + (sub & 1) * 8 + rl;
                    unsigned bv[4];
                    ldsm4(bv, Vb + rv * 64 + SWA(rv, chunk) * 4);
                    mma_tf32(o[2 * p],     ap, bv[0], bv[2]);
                    mma_tf32(o[2 * p + 1], ap, bv[1], bv[3]);
                }
            }
        }
    }

    const int b = bh >> 4;
    const int h = bh & 15;
    const float inv0 = 1.0f / l0;
    const float inv1 = 1.0f / l1;
    float* Og = g_att + ((size_t)(b * NT + q0 + rq)) * NC + (h << 6);
#pragma unroll
    for (int nt = 0; nt < 8; nt++) {
        int col = nt * 8 + 2 * cq;
        *(float2*)(Og + col) =
            make_float2(rtf(o[nt][0] * inv0), rtf(o[nt][1] * inv0));
        *(float2*)(Og + (size_t)8 * NC + col) =
            make_float2(rtf(o[nt][2] * inv1), rtf(o[nt][3] * inv1));
    }
}

// ---------------------------------------------------------------------------
// launch
// ---------------------------------------------------------------------------
extern "C" void kernel_launch(void* const* d_in, const int* in_sizes, int n_in,
                              void* d_out, int out_size)
{
    const float* x     = (const float*)d_in[0];
    const float* Wqkv  = (const float*)d_in[1];
    const float* Wproj = (const float*)d_in[2];
    float* out = (float*)d_out;

    void *px, *pwqkv, *pwproj, *patt;
    cudaGetSymbolAddress(&px, g_x);
    cudaGetSymbolAddress(&pwqkv, g_wqkv);
    cudaGetSymbolAddress(&pwproj, g_wproj);
    cudaGetSymbolAddress(&patt, g_att);

    cudaFuncSetAttribute(gemm_tc<1>,
                         cudaFuncAttributeMaxDynamicSharedMemorySize, GEMM_SMEM);
    cudaFuncSetAttribute(gemm_tc<0>,
                         cudaFuncAttributeMaxDynamicSharedMemorySize, GEMM_SMEM);
    cudaFuncSetAttribute(attn_tc,
                         cudaFuncAttributeMaxDynamicSharedMemorySize, ATTN_SMEM);

    // 0) pre-round x; round+transpose weights to [n][k]
    cvt_kernel<<<(NM * NC / 4 + 255) / 256, 256>>>(
        (const float4*)x, (uint4*)px, NM * NC / 4);
    cvt_t_kernel<<<dim3(3 * NC / 32, NC / 32), 256>>>(
        Wqkv, (float*)pwqkv, NC, 3 * NC);
    cvt_t_kernel<<<dim3(NC / 32, NC / 32), 256>>>(
        Wproj, (float*)pwproj, NC, NC);

    // 1) qkv = x @ Wqkv -> scatter q,k [bh][t][d], v [bh][d][t]
    gemm_tc<1><<<dim3(3 * NC / BN, NM / BM), 128, GEMM_SMEM>>>(
        (const float*)px, (const float*)pwqkv, nullptr, NM, 3 * NC, NC);

    // 2) causal attention -> g_att (rounded)
    attn_tc<<<dim3(NT / 64, NBH), 128, ATTN_SMEM>>>();

    // 3) out = g_att @ Wproj
    gemm_tc<0><<<dim3(NC / BN, NM / BM), 128, GEMM_SMEM>>>(
        (const float*)patt, (const float*)pwproj, out, NM, NC, NC);
}